// round 8
// baseline (speedup 1.0000x reference)
#include <cuda_runtime.h>
#include <cuda_bf16.h>
#include <cstdint>

// ---------------- problem constants ----------------
#define LAYERS 4
#define NHEADS 4
#define H 64
#define DHD 16
#define FIN 32
#define ACT 15
#define OBSD 1500
#define HS 512
#define NOUTD 15
#define VHD 128
#define BATCH 128
#define NNODE 1000
#define TOTN (BATCH*NNODE)      // 128000
#define DEG 4
#define NEDGE (TOTN*DEG)        // 512000

#define BM 128                  // nodes per block
#define NB (TOTN/BM)            // 1000
#define NTHR 256                // 8 warps

#define SA64 72                 // smem strides in bf16 elems; 144B % 128B = 16 -> conflict-free ldmatrix
#define SA128 136               // 272B % 128B = 16

#define A64_B   (128*SA64*2)        // 18432
#define B64_B   (64*SA64*2)         // 9216
#define B128_B  (128*SA64*2)        // 18432
#define A128_B  (128*SA128*2)       // 34816
#define B64K_B  (64*SA128*2)        // 17408

#define SM_IN    (2*A64_B + 2*B64_B)    // 55296
#define SM_QKV   (2*A64_B + 2*B64_B)    // 55296
#define SM_WO    (2*A64_B + 2*B64_B)    // 55296
#define SM_FFN1  (2*A64_B + 2*B128_B)   // 73728
#define SM_FFN2  (2*A128_B + 2*B64K_B)  // 104448

// ---------------- scratch ----------------
__device__ __align__(16) float g_x[TOTN*H];
__device__ __align__(16) float g_q[TOTN*H];
__device__ __align__(16) float g_k[TOTN*H];
__device__ __align__(16) float g_v[TOTN*H];
__device__ __align__(16) float g_agg[TOTN*H];
__device__ __align__(16) float g_hid[TOTN*2*H];
__device__ int g_deg[TOTN];
__device__ int g_rowptr[TOTN+1];
__device__ int g_cursor[TOTN];
__device__ int g_srcs[NEDGE];
__device__ float g_gat[BATCH*ACT];
__device__ __align__(16) float g_feat[BATCH*HS];
__device__ __align__(16) float g_feat2[BATCH*HS];
__device__ __align__(16) float g_vh[BATCH*VHD];
__device__ __align__(16) float g_vh2[BATCH*VHD];

// ---------------- mma / ldmatrix primitives ----------------
__device__ __forceinline__ uint32_t smem_u32(const void* p){
    uint32_t a;
    asm("{ .reg .u64 t; cvta.to.shared.u64 t, %1; cvt.u32.u64 %0, t; }" : "=r"(a) : "l"(p));
    return a;
}
__device__ __forceinline__ void ldsm4(uint32_t* r, uint32_t addr){
    asm volatile("ldmatrix.sync.aligned.m8n8.x4.shared.b16 {%0,%1,%2,%3}, [%4];"
        : "=r"(r[0]),"=r"(r[1]),"=r"(r[2]),"=r"(r[3]) : "r"(addr));
}
__device__ __forceinline__ void mma4(float* c, const uint32_t* a, uint32_t b0, uint32_t b1){
    asm volatile("mma.sync.aligned.m16n8k16.row.col.f32.bf16.bf16.f32 "
        "{%0,%1,%2,%3}, {%4,%5,%6,%7}, {%8,%9}, {%0,%1,%2,%3};"
        : "+f"(c[0]),"+f"(c[1]),"+f"(c[2]),"+f"(c[3])
        : "r"(a[0]),"r"(a[1]),"r"(a[2]),"r"(a[3]), "r"(b0),"r"(b1));
}
__device__ __forceinline__ void pack2(float v0, float v1, uint32_t& hp, uint32_t& lp){
    __nv_bfloat16 h0 = __float2bfloat16(v0), h1 = __float2bfloat16(v1);
    float r0 = v0 - __bfloat162float(h0), r1 = v1 - __bfloat162float(h1);
    __nv_bfloat16 l0 = __float2bfloat16(r0), l1 = __float2bfloat16(r1);
    hp = ((uint32_t)__bfloat16_as_ushort(h1) << 16) | __bfloat16_as_ushort(h0);
    lp = ((uint32_t)__bfloat16_as_ushort(l1) << 16) | __bfloat16_as_ushort(l0);
}

template<int ROWS, int KC, int SAe>
__device__ __forceinline__ void stage_A(const float* __restrict__ g, int rs,
                                        char* hi, char* lo, int tid){
    for (int idx = tid; idx < ROWS*(KC/8); idx += NTHR){
        int row = idx / (KC/8), c8 = (idx % (KC/8)) * 8;
        float4 f0 = *(const float4*)(g + (size_t)row*rs + c8);
        float4 f1 = *(const float4*)(g + (size_t)row*rs + c8 + 4);
        float v[8] = {f0.x,f0.y,f0.z,f0.w,f1.x,f1.y,f1.z,f1.w};
        uint32_t hp[4], lp[4];
#pragma unroll
        for (int j = 0; j < 4; j++) pack2(v[2*j], v[2*j+1], hp[j], lp[j]);
        *(uint4*)(hi + row*SAe*2 + c8*2) = make_uint4(hp[0],hp[1],hp[2],hp[3]);
        *(uint4*)(lo + row*SAe*2 + c8*2) = make_uint4(lp[0],lp[1],lp[2],lp[3]);
    }
}
template<int NN, int KC, int SBe>
__device__ __forceinline__ void stage_B(const float* __restrict__ W, int ns,
                                        char* hi, char* lo, int tid){
    for (int idx = tid; idx < NN*(KC/8); idx += NTHR){
        int n = idx / (KC/8), k8 = (idx % (KC/8)) * 8;
        uint32_t hp[4], lp[4];
#pragma unroll
        for (int j = 0; j < 4; j++){
            float v0 = __ldg(W + (size_t)(k8+2*j)*ns + n);
            float v1 = __ldg(W + (size_t)(k8+2*j+1)*ns + n);
            pack2(v0, v1, hp[j], lp[j]);
        }
        *(uint4*)(hi + n*SBe*2 + k8*2) = make_uint4(hp[0],hp[1],hp[2],hp[3]);
        *(uint4*)(lo + n*SBe*2 + k8*2) = make_uint4(lp[0],lp[1],lp[2],lp[3]);
    }
}

template<int NT, int KS, int SAe, int SBe>
__device__ __forceinline__ void mma_loop(const char* A_hi, const char* A_lo,
                                         const char* B_hi, const char* B_lo,
                                         int lane, int m0, float acc[][4]){
    int q = lane >> 3, r = lane & 7;
    uint32_t aoff = (uint32_t)(m0 + ((q & 1) << 3) + r) * (SAe*2) + (((q >> 1) << 3) * 2);
    uint32_t ah = smem_u32(A_hi) + aoff, al = smem_u32(A_lo) + aoff;
    uint32_t boff = (uint32_t)(((q >> 1) << 3) + r) * (SBe*2) + (((q & 1) << 3) * 2);
    uint32_t bh0 = smem_u32(B_hi) + boff, bl0 = smem_u32(B_lo) + boff;
#pragma unroll
    for (int kk = 0; kk < KS; kk++){
        uint32_t af[4], alf[4];
        ldsm4(af,  ah + kk*32);
        ldsm4(alf, al + kk*32);
#pragma unroll
        for (int g2 = 0; g2 < NT/2; g2++){
            uint32_t bf[4], blf[4];
            ldsm4(bf,  bh0 + g2*16*(SBe*2) + kk*32);
            ldsm4(blf, bl0 + g2*16*(SBe*2) + kk*32);
            mma4(acc[g2*2],   af,  bf[0],  bf[1]);
            mma4(acc[g2*2+1], af,  bf[2],  bf[3]);
            mma4(acc[g2*2],   af,  blf[0], blf[1]);
            mma4(acc[g2*2+1], af,  blf[2], blf[3]);
            mma4(acc[g2*2],   alf, bf[0],  bf[1]);
            mma4(acc[g2*2+1], alf, bf[2],  bf[3]);
        }
    }
}
template<int NT>
__device__ __forceinline__ void zero_acc(float acc[][4]){
#pragma unroll
    for (int i = 0; i < NT; i++){ acc[i][0]=0; acc[i][1]=0; acc[i][2]=0; acc[i][3]=0; }
}
template<int NT, bool RELU>
__device__ __forceinline__ void store_frags(float* __restrict__ g, int rs, int m0,
                                            int lane, float acc[][4],
                                            const float* __restrict__ bias){
    int r = lane >> 2, c2 = (lane & 3) * 2;
#pragma unroll
    for (int nt = 0; nt < NT; nt++){
        int col = nt*8 + c2;
        float b0 = bias ? __ldg(bias+col) : 0.f;
        float b1 = bias ? __ldg(bias+col+1) : 0.f;
        float v0 = acc[nt][0]+b0, v1 = acc[nt][1]+b1;
        float v2 = acc[nt][2]+b0, v3 = acc[nt][3]+b1;
        if (RELU){ v0=fmaxf(v0,0.f); v1=fmaxf(v1,0.f); v2=fmaxf(v2,0.f); v3=fmaxf(v3,0.f); }
        *(float2*)(g + (size_t)(m0+r)*rs + col)   = make_float2(v0, v1);
        *(float2*)(g + (size_t)(m0+r+8)*rs + col) = make_float2(v2, v3);
    }
}
template<int NT>
__device__ __forceinline__ void stage_frags(float* sOut, int m0, int lane, float acc[][4]){
    int r = lane >> 2, c2 = (lane & 3) * 2;
#pragma unroll
    for (int nt = 0; nt < NT; nt++){
        int col = nt*8 + c2;
        *(float2*)(sOut + (m0+r)*66 + col)   = make_float2(acc[nt][0], acc[nt][1]);
        *(float2*)(sOut + (m0+r+8)*66 + col) = make_float2(acc[nt][2], acc[nt][3]);
    }
}
__device__ __forceinline__ void ln_row(const float* sOut, int node, int row,
                                       const float* __restrict__ bias,
                                       const float* __restrict__ lg,
                                       const float* __restrict__ lb){
    float o[H];
#pragma unroll
    for (int i = 0; i < H; i++) o[i] = sOut[row*66 + i];
    const float4* xp = (const float4*)(g_x + (size_t)node * H);
#pragma unroll
    for (int i = 0; i < 16; i++){
        float4 f = xp[i];
        o[4*i+0] += f.x; o[4*i+1] += f.y; o[4*i+2] += f.z; o[4*i+3] += f.w;
    }
    if (bias){
#pragma unroll
        for (int i = 0; i < H; i++) o[i] += __ldg(&bias[i]);
    }
    float mean = 0.f;
#pragma unroll
    for (int i = 0; i < H; i++) mean += o[i];
    mean *= (1.f / H);
    float var = 0.f;
#pragma unroll
    for (int i = 0; i < H; i++){ float d = o[i] - mean; var += d * d; }
    var *= (1.f / H);
    float rr = rsqrtf(var + 1e-5f);
    float4* op = (float4*)(g_x + (size_t)node * H);
#pragma unroll
    for (int i = 0; i < 16; i++){
        op[i] = make_float4(
            (o[4*i+0]-mean)*rr*__ldg(&lg[4*i+0]) + __ldg(&lb[4*i+0]),
            (o[4*i+1]-mean)*rr*__ldg(&lg[4*i+1]) + __ldg(&lb[4*i+1]),
            (o[4*i+2]-mean)*rr*__ldg(&lg[4*i+2]) + __ldg(&lb[4*i+2]),
            (o[4*i+3]-mean)*rr*__ldg(&lg[4*i+3]) + __ldg(&lb[4*i+3]));
    }
}

// ---------------- CSR build ----------------
__global__ void k_zero_deg(){
    int i = blockIdx.x * 256 + threadIdx.x;
    if (i < TOTN) g_deg[i] = 0;
}
__global__ void k_hist(const int* __restrict__ edst){
    int e = blockIdx.x * 256 + threadIdx.x;
    if (e < NEDGE) atomicAdd(&g_deg[edst[e]], 1);
}
__global__ void k_scan(){
    __shared__ int ssum[1024];
    int t = threadIdx.x;
    int base = t * 125;
    int s = 0;
    for (int i = 0; i < 125; i++) s += g_deg[base + i];
    ssum[t] = s;
    __syncthreads();
    if (t == 0){
        int run = 0;
        for (int i = 0; i < 1024; i++){ int v = ssum[i]; ssum[i] = run; run += v; }
    }
    __syncthreads();
    int run = ssum[t];
    for (int i = 0; i < 125; i++){
        g_rowptr[base + i] = run;
        g_cursor[base + i] = run;
        run += g_deg[base + i];
    }
    if (t == 1023) g_rowptr[TOTN] = run;
}
__global__ void k_scatter(const int* __restrict__ esrc, const int* __restrict__ edst){
    int e = blockIdx.x * 256 + threadIdx.x;
    if (e < NEDGE){
        int d = edst[e];
        int pos = atomicAdd(&g_cursor[d], 1);
        g_srcs[pos] = esrc[e];
    }
}

// ---------------- HMMA GEMM kernels (256 threads, 8 warps, warp = 16 rows) ----------------
__global__ __launch_bounds__(NTHR) void k_input(const float* __restrict__ nf,
                                                const float* __restrict__ Win){
    extern __shared__ __align__(16) char sm[];
    char* A_hi = sm;              char* A_lo = A_hi + A64_B;
    char* B_hi = A_lo + A64_B;    char* B_lo = B_hi + B64_B;
    int tid = threadIdx.x, wid = tid >> 5, lane = tid & 31;
    int node0 = blockIdx.x * BM;
    stage_A<128, FIN, SA64>(nf + (size_t)node0 * FIN, FIN, A_hi, A_lo, tid);
    stage_B<64, FIN, SA64>(Win, 64, B_hi, B_lo, tid);
    __syncthreads();
    float acc[8][4]; zero_acc<8>(acc);
    mma_loop<8, 2, SA64, SA64>(A_hi, A_lo, B_hi, B_lo, lane, wid*16, acc);
    store_frags<8, false>(g_x + (size_t)node0 * H, H, wid*16, lane, acc, nullptr);
}

__global__ __launch_bounds__(NTHR) void k_qkv(const float* __restrict__ Wq,
                                              const float* __restrict__ Wk,
                                              const float* __restrict__ Wv){
    extern __shared__ __align__(16) char sm[];
    char* A_hi = sm;              char* A_lo = A_hi + A64_B;
    char* B_hi = A_lo + A64_B;    char* B_lo = B_hi + B64_B;
    int tid = threadIdx.x, wid = tid >> 5, lane = tid & 31;
    int node0 = blockIdx.x * BM;
    stage_A<128, H, SA64>(g_x + (size_t)node0 * H, H, A_hi, A_lo, tid);
    const float* Ws[3] = { Wq, Wk, Wv };
    float* outs[3] = { g_q, g_k, g_v };
#pragma unroll
    for (int m = 0; m < 3; m++){
        if (m > 0) __syncthreads();
        stage_B<64, H, SA64>(Ws[m], 64, B_hi, B_lo, tid);
        __syncthreads();
        float acc[8][4]; zero_acc<8>(acc);
        mma_loop<8, 4, SA64, SA64>(A_hi, A_lo, B_hi, B_lo, lane, wid*16, acc);
        store_frags<8, false>(outs[m] + (size_t)node0 * H, H, wid*16, lane, acc, nullptr);
    }
}

__global__ __launch_bounds__(NTHR) void k_wo_ln(const float* __restrict__ Wo,
                                                const float* __restrict__ lg,
                                                const float* __restrict__ lb){
    extern __shared__ __align__(16) char sm[];
    char* A_hi = sm;              char* A_lo = A_hi + A64_B;
    char* B_hi = A_lo + A64_B;    char* B_lo = B_hi + B64_B;
    int tid = threadIdx.x, wid = tid >> 5, lane = tid & 31;
    int node0 = blockIdx.x * BM;
    stage_A<128, H, SA64>(g_agg + (size_t)node0 * H, H, A_hi, A_lo, tid);
    stage_B<64, H, SA64>(Wo, 64, B_hi, B_lo, tid);
    __syncthreads();
    float acc[8][4]; zero_acc<8>(acc);
    mma_loop<8, 4, SA64, SA64>(A_hi, A_lo, B_hi, B_lo, lane, wid*16, acc);
    __syncthreads();                         // A region dead
    float* sOut = (float*)sm;                // 128 x 66 fp32 = 33792 <= 36864
    stage_frags<8>(sOut, wid*16, lane, acc);
    __syncthreads();
    if (tid < 128) ln_row(sOut, node0 + tid, tid, nullptr, lg, lb);
}

__global__ __launch_bounds__(NTHR) void k_ffn1(const float* __restrict__ W1,
                                               const float* __restrict__ b1){
    extern __shared__ __align__(16) char sm[];
    char* A_hi = sm;              char* A_lo = A_hi + A64_B;
    char* B_hi = A_lo + A64_B;    char* B_lo = B_hi + B128_B;
    int tid = threadIdx.x, wid = tid >> 5, lane = tid & 31;
    int node0 = blockIdx.x * BM;
    stage_A<128, H, SA64>(g_x + (size_t)node0 * H, H, A_hi, A_lo, tid);
    stage_B<128, H, SA64>(W1, 2*H, B_hi, B_lo, tid);
    __syncthreads();
    float acc[16][4]; zero_acc<16>(acc);
    mma_loop<16, 4, SA64, SA64>(A_hi, A_lo, B_hi, B_lo, lane, wid*16, acc);
    store_frags<16, true>(g_hid + (size_t)node0 * (2*H), 2*H, wid*16, lane, acc, b1);
}

__global__ __launch_bounds__(NTHR) void k_ffn2(const float* __restrict__ W2,
                                               const float* __restrict__ b2,
                                               const float* __restrict__ lg,
                                               const float* __restrict__ lb){
    extern __shared__ __align__(16) char sm[];
    char* A_hi = sm;              char* A_lo = A_hi + A128_B;
    char* B_hi = A_lo + A128_B;   char* B_lo = B_hi + B64K_B;
    int tid = threadIdx.x, wid = tid >> 5, lane = tid & 31;
    int node0 = blockIdx.x * BM;
    stage_A<128, 2*H, SA128>(g_hid + (size_t)node0 * (2*H), 2*H, A_hi, A_lo, tid);
    stage_B<64, 2*H, SA128>(W2, 64, B_hi, B_lo, tid);
    __syncthreads();
    float acc[8][4]; zero_acc<8>(acc);
    mma_loop<8, 8, SA128, SA128>(A_hi, A_lo, B_hi, B_lo, lane, wid*16, acc);
    __syncthreads();
    float* sOut = (float*)sm;                // 33792 <= 2*A128_B
    stage_frags<8>(sOut, wid*16, lane, acc);
    __syncthreads();
    if (tid < 128) ln_row(sOut, node0 + tid, tid, b2, lg, lb);
}

// ---------------- warp-per-node attention (online softmax) ----------------
__global__ __launch_bounds__(256) void k_attn(){
    int warp = (blockIdx.x * 256 + threadIdx.x) >> 5;
    int lane = threadIdx.x & 31;
    if (warp >= TOTN) return;
    int node = warp;
    float2 q = *(const float2*)(g_q + (size_t)node * H + 2*lane);
    int s0 = g_rowptr[node], s1 = g_rowptr[node + 1];
    float m = -1e30f, den = 0.f, ax = 0.f, ay = 0.f;
    for (int e = s0; e < s1; e++){
        int src = g_srcs[e];
        float2 kk = *(const float2*)(g_k + (size_t)src * H + 2*lane);
        float2 vv = *(const float2*)(g_v + (size_t)src * H + 2*lane);
        float p = q.x * kk.x + q.y * kk.y;
        p += __shfl_xor_sync(0xffffffffu, p, 1);
        p += __shfl_xor_sync(0xffffffffu, p, 2);
        p += __shfl_xor_sync(0xffffffffu, p, 4);
        float s = p * 0.25f;
        float mn = fmaxf(m, s);
        float scale = __expf(m - mn);
        float w = __expf(s - mn);
        den = den * scale + w;
        ax = ax * scale + w * vv.x;
        ay = ay * scale + w * vv.y;
        m = mn;
    }
    float inv = 1.f / (den + 1e-9f);
    *(float2*)(g_agg + (size_t)node * H + 2*lane) = make_float2(ax * inv, ay * inv);
}

// ---------------- readout + heads ----------------
__global__ void k_gat(const int* __restrict__ an, const float* __restrict__ Wr,
                      const float* __restrict__ br){
    __shared__ float sW[H*ACT];
    __shared__ float sb[ACT];
    int tid = threadIdx.x;
    for (int i = tid; i < H*ACT; i += 128) sW[i] = Wr[i];
    if (tid < ACT) sb[tid] = br[tid];
    __syncthreads();
    int b = tid;
    int node = an[b];
    float acc[ACT];
#pragma unroll
    for (int j = 0; j < ACT; j++) acc[j] = sb[j];
    for (int i = 0; i < H; i++){
        float xi = g_x[(size_t)node * H + i];
#pragma unroll
        for (int j = 0; j < ACT; j++) acc[j] += xi * sW[i*ACT + j];
    }
#pragma unroll
    for (int j = 0; j < ACT; j++) g_gat[b*ACT + j] = acc[j];
}

__global__ __launch_bounds__(512) void k_policy1(const float* __restrict__ obs,
                                                 const float* __restrict__ Wp1,
                                                 const float* __restrict__ bp1){
    __shared__ float sr[ACT + OBSD];
    int b = blockIdx.x;
    for (int i = threadIdx.x; i < ACT; i += 512) sr[i] = g_gat[b*ACT + i];
    for (int i = threadIdx.x; i < OBSD; i += 512) sr[ACT + i] = obs[(size_t)b*OBSD + i];
    __syncthreads();
    int j = threadIdx.x;
    const float* W = Wp1 + j;
    float a0 = 0, a1 = 0, a2 = 0, a3 = 0;
    int i = 0;
    const int K = ACT + OBSD;
    for (; i + 3 < K; i += 4){
        a0 += sr[i+0] * W[(size_t)(i+0)*HS];
        a1 += sr[i+1] * W[(size_t)(i+1)*HS];
        a2 += sr[i+2] * W[(size_t)(i+2)*HS];
        a3 += sr[i+3] * W[(size_t)(i+3)*HS];
    }
    for (; i < K; i++) a0 += sr[i] * W[(size_t)i*HS];
    g_feat[b*HS + j] = tanhf(a0 + a1 + a2 + a3 + bp1[j]);
}

__global__ __launch_bounds__(512) void k_policy2(const float* __restrict__ Wp2,
                                                 const float* __restrict__ bp2){
    __shared__ float sr[HS];
    int b = blockIdx.x;
    for (int i = threadIdx.x; i < HS; i += 512) sr[i] = g_feat[b*HS + i];
    __syncthreads();
    int j = threadIdx.x;
    const float* W = Wp2 + j;
    float a0 = 0, a1 = 0, a2 = 0, a3 = 0;
    for (int i = 0; i < HS; i += 4){
        a0 += sr[i+0] * W[(size_t)(i+0)*HS];
        a1 += sr[i+1] * W[(size_t)(i+1)*HS];
        a2 += sr[i+2] * W[(size_t)(i+2)*HS];
        a3 += sr[i+3] * W[(size_t)(i+3)*HS];
    }
    g_feat2[b*HS + j] = tanhf(a0 + a1 + a2 + a3 + bp2[j]);
}

__global__ void k_logits(const float* __restrict__ Wlog, const float* __restrict__ blog,
                         float* __restrict__ out){
    int b = blockIdx.x;
    int j = threadIdx.x;
    if (j >= NOUTD) return;
    float acc = blog[j];
    for (int i = 0; i < HS; i++) acc += g_feat2[b*HS + i] * Wlog[i*NOUTD + j];
    out[b*NOUTD + j] = acc;
}

__global__ __launch_bounds__(VHD) void k_value1(const float* __restrict__ obs,
                                                const float* __restrict__ Wv1,
                                                const float* __restrict__ bv1){
    __shared__ float sr[OBSD];
    int b = blockIdx.x;
    for (int i = threadIdx.x; i < OBSD; i += VHD) sr[i] = obs[(size_t)b*OBSD + i];
    __syncthreads();
    int j = threadIdx.x;
    const float* W = Wv1 + j;
    float a0 = 0, a1 = 0, a2 = 0, a3 = 0;
    for (int i = 0; i < OBSD; i += 4){
        a0 += sr[i+0] * W[(size_t)(i+0)*VHD];
        a1 += sr[i+1] * W[(size_t)(i+1)*VHD];
        a2 += sr[i+2] * W[(size_t)(i+2)*VHD];
        a3 += sr[i+3] * W[(size_t)(i+3)*VHD];
    }
    g_vh[b*VHD + j] = tanhf(a0 + a1 + a2 + a3 + bv1[j]);
}

__global__ __launch_bounds__(VHD) void k_value2(const float* __restrict__ Wv2,
                                                const float* __restrict__ bv2){
    __shared__ float sr[VHD];
    int b = blockIdx.x;
    sr[threadIdx.x] = g_vh[b*VHD + threadIdx.x];
    __syncthreads();
    int j = threadIdx.x;
    const float* W = Wv2 + j;
    float a0 = 0, a1 = 0, a2 = 0, a3 = 0;
    for (int i = 0; i < VHD; i += 4){
        a0 += sr[i+0] * W[(i+0)*VHD];
        a1 += sr[i+1] * W[(i+1)*VHD];
        a2 += sr[i+2] * W[(i+2)*VHD];
        a3 += sr[i+3] * W[(i+3)*VHD];
    }
    g_vh2[b*VHD + j] = tanhf(a0 + a1 + a2 + a3 + bv2[j]);
}

__global__ void k_valueout(const float* __restrict__ Wvo, const float* __restrict__ bvo,
                           float* __restrict__ out){
    int b = threadIdx.x;
    float acc = bvo[0];
    for (int i = 0; i < VHD; i++) acc += g_vh2[b*VHD + i] * Wvo[i];
    out[BATCH*NOUTD + b] = acc;
}

// ---------------- launch ----------------
extern "C" void kernel_launch(void* const* d_in, const int* in_sizes, int n_in,
                              void* d_out, int out_size){
    const float* node_feats = (const float*)d_in[0];
    const float* obs        = (const float*)d_in[1];
    const int*   edge_src   = (const int*)  d_in[2];
    const int*   edge_dst   = (const int*)  d_in[3];
    const int*   agent      = (const int*)  d_in[4];
    const float* W_in  = (const float*)d_in[5];
    const float* Wq    = (const float*)d_in[6];
    const float* Wk    = (const float*)d_in[7];
    const float* Wv    = (const float*)d_in[8];
    const float* Wo    = (const float*)d_in[9];
    const float* ln1g  = (const float*)d_in[10];
    const float* ln1b  = (const float*)d_in[11];
    const float* W1    = (const float*)d_in[12];
    const float* b1    = (const float*)d_in[13];
    const float* W2    = (const float*)d_in[14];
    const float* b2    = (const float*)d_in[15];
    const float* ln2g  = (const float*)d_in[16];
    const float* ln2b  = (const float*)d_in[17];
    const float* Wr    = (const float*)d_in[18];
    const float* br    = (const float*)d_in[19];
    const float* Wp1   = (const float*)d_in[20];
    const float* bp1   = (const float*)d_in[21];
    const float* Wp2   = (const float*)d_in[22];
    const float* bp2   = (const float*)d_in[23];
    const float* Wlog  = (const float*)d_in[24];
    const float* blog  = (const float*)d_in[25];
    const float* Wv1   = (const float*)d_in[26];
    const float* bv1   = (const float*)d_in[27];
    const float* Wv2   = (const float*)d_in[28];
    const float* bv2   = (const float*)d_in[29];
    const float* Wvo   = (const float*)d_in[30];
    const float* bvo   = (const float*)d_in[31];
    float* out = (float*)d_out;

    cudaFuncSetAttribute((const void*)k_input, cudaFuncAttributeMaxDynamicSharedMemorySize, SM_IN);
    cudaFuncSetAttribute((const void*)k_qkv,   cudaFuncAttributeMaxDynamicSharedMemorySize, SM_QKV);
    cudaFuncSetAttribute((const void*)k_wo_ln, cudaFuncAttributeMaxDynamicSharedMemorySize, SM_WO);
    cudaFuncSetAttribute((const void*)k_ffn1,  cudaFuncAttributeMaxDynamicSharedMemorySize, SM_FFN1);
    cudaFuncSetAttribute((const void*)k_ffn2,  cudaFuncAttributeMaxDynamicSharedMemorySize, SM_FFN2);

    k_zero_deg<<<(TOTN + 255)/256, 256>>>();
    k_hist<<<(NEDGE + 255)/256, 256>>>(edge_dst);
    k_scan<<<1, 1024>>>();
    k_input<<<NB, NTHR, SM_IN>>>(node_feats, W_in);              // capture slot 4
    k_scatter<<<(NEDGE + 255)/256, 256>>>(edge_src, edge_dst);

    for (int l = 0; l < LAYERS; l++){
        k_qkv  <<<NB, NTHR, SM_QKV>>>(Wq + l*H*H, Wk + l*H*H, Wv + l*H*H);
        k_attn <<<(TOTN*32 + 255)/256, 256>>>();
        k_wo_ln<<<NB, NTHR, SM_WO>>>(Wo + l*H*H, ln1g + l*H, ln1b + l*H);
        k_ffn1 <<<NB, NTHR, SM_FFN1>>>(W1 + l*H*2*H, b1 + l*2*H);
        k_ffn2 <<<NB, NTHR, SM_FFN2>>>(W2 + l*2*H*H, b2 + l*H, ln2g + l*H, ln2b + l*H);
    }

    k_gat<<<1, 128>>>(agent, Wr, br);
    k_policy1<<<BATCH, 512>>>(obs, Wp1, bp1);
    k_policy2<<<BATCH, 512>>>(Wp2, bp2);
    k_logits<<<BATCH, 32>>>(Wlog, blog, out);
    k_value1<<<BATCH, VHD>>>(obs, Wv1, bv1);
    k_value2<<<BATCH, VHD>>>(Wv2, bv2);
    k_valueout<<<1, BATCH>>>(Wvo, bvo, out);
}

// round 9
// speedup vs baseline: 1.5341x; 1.5341x over previous
#include <cuda_runtime.h>
#include <cuda_bf16.h>
#include <cstdint>

// ---------------- problem constants ----------------
#define LAYERS 4
#define NHEADS 4
#define H 64
#define DHD 16
#define FIN 32
#define ACT 15
#define OBSD 1500
#define HS 512
#define NOUTD 15
#define VHD 128
#define BATCH 128
#define NNODE 1000
#define TOTN (BATCH*NNODE)      // 128000
#define DEG 4
#define NEDGE (TOTN*DEG)        // 512000

#define BM 128
#define NB (TOTN/BM)            // 1000
#define NTHR 256                // 8 warps

#define SA64 72                 // bf16-elem stride; 144B%128B=16 -> conflict-free ldmatrix
#define A64_B   (128*SA64*2)    // 18432 per hi/lo component
#define B64_B   (64*SA64*2)     // 9216 per component

// fused-layer smem regions (bytes)
#define R_X   0                  // x hi/lo: 36864
#define R_B   36864              // weight tile hi/lo: 18432
#define R_H   55296              // agg A / sOut / hid half hi/lo: 36864
#define SM_LAYER 92160           // 2 CTAs/SM

// ---------------- scratch ----------------
__device__ __align__(16) float g_x[TOTN*H];
__device__ __align__(16) float g_q[TOTN*H];
__device__ __align__(16) float g_k[TOTN*H];
__device__ __align__(16) float g_v[TOTN*H];
__device__ __align__(16) float g_agg[TOTN*H];
__device__ int g_deg[TOTN];
__device__ int g_rowptr[TOTN+1];
__device__ int g_cursor[TOTN];
__device__ int g_srcs[NEDGE];
__device__ float g_gat[BATCH*ACT];
__device__ __align__(16) float g_feat[BATCH*HS];
__device__ __align__(16) float g_feat2[BATCH*HS];
__device__ __align__(16) float g_vh[BATCH*VHD];
__device__ __align__(16) float g_vh2[BATCH*VHD];

// ---------------- mma / ldmatrix primitives ----------------
__device__ __forceinline__ uint32_t smem_u32(const void* p){
    uint32_t a;
    asm("{ .reg .u64 t; cvta.to.shared.u64 t, %1; cvt.u32.u64 %0, t; }" : "=r"(a) : "l"(p));
    return a;
}
__device__ __forceinline__ void ldsm4(uint32_t* r, uint32_t addr){
    asm volatile("ldmatrix.sync.aligned.m8n8.x4.shared.b16 {%0,%1,%2,%3}, [%4];"
        : "=r"(r[0]),"=r"(r[1]),"=r"(r[2]),"=r"(r[3]) : "r"(addr));
}
__device__ __forceinline__ void mma4(float* c, const uint32_t* a, uint32_t b0, uint32_t b1){
    asm volatile("mma.sync.aligned.m16n8k16.row.col.f32.bf16.bf16.f32 "
        "{%0,%1,%2,%3}, {%4,%5,%6,%7}, {%8,%9}, {%0,%1,%2,%3};"
        : "+f"(c[0]),"+f"(c[1]),"+f"(c[2]),"+f"(c[3])
        : "r"(a[0]),"r"(a[1]),"r"(a[2]),"r"(a[3]), "r"(b0),"r"(b1));
}
__device__ __forceinline__ void pack2(float v0, float v1, uint32_t& hp, uint32_t& lp){
    __nv_bfloat16 h0 = __float2bfloat16(v0), h1 = __float2bfloat16(v1);
    float r0 = v0 - __bfloat162float(h0), r1 = v1 - __bfloat162float(h1);
    __nv_bfloat16 l0 = __float2bfloat16(r0), l1 = __float2bfloat16(r1);
    hp = ((uint32_t)__bfloat16_as_ushort(h1) << 16) | __bfloat16_as_ushort(h0);
    lp = ((uint32_t)__bfloat16_as_ushort(l1) << 16) | __bfloat16_as_ushort(l0);
}

// stage 128xKC fp32 (row stride rs) -> hi/lo bf16 smem at SA64
template<int KC>
__device__ __forceinline__ void stage_A(const float* __restrict__ g, int rs,
                                        char* hi, char* lo, int tid){
    for (int idx = tid; idx < 128*(KC/8); idx += NTHR){
        int row = idx / (KC/8), c8 = (idx % (KC/8)) * 8;
        float4 f0 = *(const float4*)(g + (size_t)row*rs + c8);
        float4 f1 = *(const float4*)(g + (size_t)row*rs + c8 + 4);
        float v[8] = {f0.x,f0.y,f0.z,f0.w,f1.x,f1.y,f1.z,f1.w};
        uint32_t hp[4], lp[4];
#pragma unroll
        for (int j = 0; j < 4; j++) pack2(v[2*j], v[2*j+1], hp[j], lp[j]);
        *(uint4*)(hi + row*SA64*2 + c8*2) = make_uint4(hp[0],hp[1],hp[2],hp[3]);
        *(uint4*)(lo + row*SA64*2 + c8*2) = make_uint4(lp[0],lp[1],lp[2],lp[3]);
    }
}
// stage W[KC][64] (row stride ns) transposed -> B[n][k] hi/lo at SA64
template<int KC>
__device__ __forceinline__ void stage_B(const float* __restrict__ W, int ns,
                                        char* hi, char* lo, int tid){
    for (int idx = tid; idx < 64*(KC/8); idx += NTHR){
        int n = idx / (KC/8), k8 = (idx % (KC/8)) * 8;
        uint32_t hp[4], lp[4];
#pragma unroll
        for (int j = 0; j < 4; j++){
            float v0 = __ldg(W + (size_t)(k8+2*j)*ns + n);
            float v1 = __ldg(W + (size_t)(k8+2*j+1)*ns + n);
            pack2(v0, v1, hp[j], lp[j]);
        }
        *(uint4*)(hi + n*SA64*2 + k8*2) = make_uint4(hp[0],hp[1],hp[2],hp[3]);
        *(uint4*)(lo + n*SA64*2 + k8*2) = make_uint4(lp[0],lp[1],lp[2],lp[3]);
    }
}

// warp mma: 16 rows x 64 cols, KS k16-steps, hi/lo 3-term
template<int KS>
__device__ __forceinline__ void mma_loop(const char* A_hi, const char* A_lo,
                                         const char* B_hi, const char* B_lo,
                                         int lane, int m0, float acc[][4]){
    int q = lane >> 3, r = lane & 7;
    uint32_t aoff = (uint32_t)(m0 + ((q & 1) << 3) + r) * (SA64*2) + (((q >> 1) << 3) * 2);
    uint32_t ah = smem_u32(A_hi) + aoff, al = smem_u32(A_lo) + aoff;
    uint32_t boff = (uint32_t)(((q >> 1) << 3) + r) * (SA64*2) + (((q & 1) << 3) * 2);
    uint32_t bh0 = smem_u32(B_hi) + boff, bl0 = smem_u32(B_lo) + boff;
#pragma unroll
    for (int kk = 0; kk < KS; kk++){
        uint32_t af[4], alf[4];
        ldsm4(af,  ah + kk*32);
        ldsm4(alf, al + kk*32);
#pragma unroll
        for (int g2 = 0; g2 < 4; g2++){
            uint32_t bf[4], blf[4];
            ldsm4(bf,  bh0 + g2*16*(SA64*2) + kk*32);
            ldsm4(blf, bl0 + g2*16*(SA64*2) + kk*32);
            mma4(acc[g2*2],   af,  bf[0],  bf[1]);
            mma4(acc[g2*2+1], af,  bf[2],  bf[3]);
            mma4(acc[g2*2],   af,  blf[0], blf[1]);
            mma4(acc[g2*2+1], af,  blf[2], blf[3]);
            mma4(acc[g2*2],   alf, bf[0],  bf[1]);
            mma4(acc[g2*2+1], alf, bf[2],  bf[3]);
        }
    }
}
__device__ __forceinline__ void zero8(float acc[][4]){
#pragma unroll
    for (int i = 0; i < 8; i++){ acc[i][0]=0; acc[i][1]=0; acc[i][2]=0; acc[i][3]=0; }
}
__device__ __forceinline__ void store_frags8(float* __restrict__ g, int rs, int m0,
                                             int lane, float acc[][4]){
    int r = lane >> 2, c2 = (lane & 3) * 2;
#pragma unroll
    for (int nt = 0; nt < 8; nt++){
        int col = nt*8 + c2;
        *(float2*)(g + (size_t)(m0+r)*rs + col)   = make_float2(acc[nt][0], acc[nt][1]);
        *(float2*)(g + (size_t)(m0+r+8)*rs + col) = make_float2(acc[nt][2], acc[nt][3]);
    }
}
__device__ __forceinline__ void stage_frags8(float* sOut, int m0, int lane, float acc[][4]){
    int r = lane >> 2, c2 = (lane & 3) * 2;
#pragma unroll
    for (int nt = 0; nt < 8; nt++){
        int col = nt*8 + c2;
        *(float2*)(sOut + (m0+r)*66 + col)   = make_float2(acc[nt][0], acc[nt][1]);
        *(float2*)(sOut + (m0+r+8)*66 + col) = make_float2(acc[nt][2], acc[nt][3]);
    }
}
// relu(acc+bias) frags -> hid hi/lo smem (64 local cols)
__device__ __forceinline__ void frag_relu_pack(char* Hhi, char* Hlo, int m0, int lane,
                                               float acc[][4], const float* __restrict__ bias){
    int r = lane >> 2, c2 = (lane & 3) * 2;
#pragma unroll
    for (int nt = 0; nt < 8; nt++){
        int col = nt*8 + c2;
        float b0 = __ldg(bias+col), b1 = __ldg(bias+col+1);
        float v0 = fmaxf(acc[nt][0]+b0, 0.f), v1 = fmaxf(acc[nt][1]+b1, 0.f);
        float v2 = fmaxf(acc[nt][2]+b0, 0.f), v3 = fmaxf(acc[nt][3]+b1, 0.f);
        uint32_t hp, lp;
        pack2(v0, v1, hp, lp);
        *(uint32_t*)(Hhi + (m0+r)*SA64*2 + col*2) = hp;
        *(uint32_t*)(Hlo + (m0+r)*SA64*2 + col*2) = lp;
        pack2(v2, v3, hp, lp);
        *(uint32_t*)(Hhi + (m0+r+8)*SA64*2 + col*2) = hp;
        *(uint32_t*)(Hlo + (m0+r+8)*SA64*2 + col*2) = lp;
    }
}
// LN(+residual,+bias) from sOut row -> g_x fp32 AND hi/lo pack into X region
__device__ __forceinline__ void ln_pack_row(const float* sOut, int node, int row,
                                            const float* __restrict__ bias,
                                            const float* __restrict__ lg,
                                            const float* __restrict__ lb,
                                            char* Xhi, char* Xlo){
    float o[H];
#pragma unroll
    for (int i = 0; i < H; i++) o[i] = sOut[row*66 + i];
    const float4* xp = (const float4*)(g_x + (size_t)node * H);
#pragma unroll
    for (int i = 0; i < 16; i++){
        float4 f = xp[i];
        o[4*i+0] += f.x; o[4*i+1] += f.y; o[4*i+2] += f.z; o[4*i+3] += f.w;
    }
    if (bias){
#pragma unroll
        for (int i = 0; i < H; i++) o[i] += __ldg(&bias[i]);
    }
    float mean = 0.f;
#pragma unroll
    for (int i = 0; i < H; i++) mean += o[i];
    mean *= (1.f / H);
    float var = 0.f;
#pragma unroll
    for (int i = 0; i < H; i++){ float d = o[i] - mean; var += d * d; }
    var *= (1.f / H);
    float rr = rsqrtf(var + 1e-5f);
    float g[H];
#pragma unroll
    for (int i = 0; i < H; i++)
        g[i] = (o[i]-mean)*rr*__ldg(&lg[i]) + __ldg(&lb[i]);
    float4* op = (float4*)(g_x + (size_t)node * H);
#pragma unroll
    for (int i = 0; i < 16; i++)
        op[i] = make_float4(g[4*i+0], g[4*i+1], g[4*i+2], g[4*i+3]);
#pragma unroll
    for (int i = 0; i < 32; i++){
        uint32_t hp, lp;
        pack2(g[2*i], g[2*i+1], hp, lp);
        *(uint32_t*)(Xhi + row*SA64*2 + i*4) = hp;
        *(uint32_t*)(Xlo + row*SA64*2 + i*4) = lp;
    }
}
// plain row (no LN) -> g_x + pack
__device__ __forceinline__ void row_store_pack(const float* sOut, int node, int row,
                                               char* Xhi, char* Xlo){
    float g[H];
#pragma unroll
    for (int i = 0; i < H; i++) g[i] = sOut[row*66 + i];
    float4* op = (float4*)(g_x + (size_t)node * H);
#pragma unroll
    for (int i = 0; i < 16; i++)
        op[i] = make_float4(g[4*i+0], g[4*i+1], g[4*i+2], g[4*i+3]);
#pragma unroll
    for (int i = 0; i < 32; i++){
        uint32_t hp, lp;
        pack2(g[2*i], g[2*i+1], hp, lp);
        *(uint32_t*)(Xhi + row*SA64*2 + i*4) = hp;
        *(uint32_t*)(Xlo + row*SA64*2 + i*4) = lp;
    }
}
// qkv from packed X -> g_q/g_k/g_v
__device__ __forceinline__ void qkv_from_x(char* Xhi, char* Xlo, char* Bhi, char* Blo,
                                           const float* Wq, const float* Wk, const float* Wv,
                                           int node0, int wid, int lane, int tid){
    const float* Ws[3] = { Wq, Wk, Wv };
    float* outs[3] = { g_q, g_k, g_v };
#pragma unroll
    for (int m = 0; m < 3; m++){
        __syncthreads();                 // prev B readers done / X pack visible
        stage_B<H>(Ws[m], 64, Bhi, Blo, tid);
        __syncthreads();
        float acc[8][4]; zero8(acc);
        mma_loop<4>(Xhi, Xlo, Bhi, Blo, lane, wid*16, acc);
        store_frags8(outs[m] + (size_t)node0 * H, H, wid*16, lane, acc);
    }
}

// ---------------- CSR build ----------------
__global__ void k_zero_deg(){
    int i = blockIdx.x * 256 + threadIdx.x;
    if (i < TOTN) g_deg[i] = 0;
}
__global__ void k_hist(const int* __restrict__ edst){
    int e = blockIdx.x * 256 + threadIdx.x;
    if (e < NEDGE) atomicAdd(&g_deg[edst[e]], 1);
}
__global__ void k_scan(){
    __shared__ int ssum[1024];
    int t = threadIdx.x;
    int base = t * 125;
    int s = 0;
    for (int i = 0; i < 125; i++) s += g_deg[base + i];
    ssum[t] = s;
    __syncthreads();
    if (t == 0){
        int run = 0;
        for (int i = 0; i < 1024; i++){ int v = ssum[i]; ssum[i] = run; run += v; }
    }
    __syncthreads();
    int run = ssum[t];
    for (int i = 0; i < 125; i++){
        g_rowptr[base + i] = run;
        g_cursor[base + i] = run;
        run += g_deg[base + i];
    }
    if (t == 1023) g_rowptr[TOTN] = run;
}
__global__ void k_scatter(const int* __restrict__ esrc, const int* __restrict__ edst){
    int e = blockIdx.x * 256 + threadIdx.x;
    if (e < NEDGE){
        int d = edst[e];
        int pos = atomicAdd(&g_cursor[d], 1);
        g_srcs[pos] = esrc[e];
    }
}

// ---------------- fused input + layer-0 qkv ----------------
__global__ __launch_bounds__(NTHR) void k_in_qkv(const float* __restrict__ nf,
                                                 const float* __restrict__ Win,
                                                 const float* __restrict__ Wq,
                                                 const float* __restrict__ Wk,
                                                 const float* __restrict__ Wv){
    extern __shared__ __align__(16) char sm[];
    char* Xhi = sm + R_X;  char* Xlo = Xhi + A64_B;
    char* Bhi = sm + R_B;  char* Blo = Bhi + B64_B;
    char* Hhi = sm + R_H;  char* Hlo = Hhi + A64_B;
    int tid = threadIdx.x, wid = tid >> 5, lane = tid & 31;
    int node0 = blockIdx.x * BM;

    stage_A<FIN>(nf + (size_t)node0 * FIN, FIN, Hhi, Hlo, tid);
    stage_B<FIN>(Win, 64, Bhi, Blo, tid);
    __syncthreads();
    float acc[8][4]; zero8(acc);
    mma_loop<2>(Hhi, Hlo, Bhi, Blo, lane, wid*16, acc);
    __syncthreads();
    float* sOut = (float*)(sm + R_H);
    stage_frags8(sOut, wid*16, lane, acc);
    __syncthreads();
    if (tid < 128) row_store_pack(sOut, node0 + tid, tid, Xhi, Xlo);

    qkv_from_x(Xhi, Xlo, Bhi, Blo, Wq, Wk, Wv, node0, wid, lane, tid);
}

// ---------------- fused layer: Wo+LN1+FFN1+FFN2+LN2 (+next qkv) ----------------
__global__ __launch_bounds__(NTHR) void k_layer(const float* __restrict__ Wo,
                                                const float* __restrict__ lg1,
                                                const float* __restrict__ lb1,
                                                const float* __restrict__ W1,
                                                const float* __restrict__ b1,
                                                const float* __restrict__ W2,
                                                const float* __restrict__ b2,
                                                const float* __restrict__ lg2,
                                                const float* __restrict__ lb2,
                                                const float* __restrict__ Wqn,
                                                const float* __restrict__ Wkn,
                                                const float* __restrict__ Wvn,
                                                int last){
    extern __shared__ __align__(16) char sm[];
    char* Xhi = sm + R_X;  char* Xlo = Xhi + A64_B;
    char* Bhi = sm + R_B;  char* Blo = Bhi + B64_B;
    char* Hhi = sm + R_H;  char* Hlo = Hhi + A64_B;
    int tid = threadIdx.x, wid = tid >> 5, lane = tid & 31;
    int node0 = blockIdx.x * BM;

    // phase 1: attn_out = agg @ Wo ; x = LN1(x + attn_out) -> g_x + X pack
    stage_A<H>(g_agg + (size_t)node0 * H, H, Hhi, Hlo, tid);
    stage_B<H>(Wo, 64, Bhi, Blo, tid);
    __syncthreads();
    {
        float acc[8][4]; zero8(acc);
        mma_loop<4>(Hhi, Hlo, Bhi, Blo, lane, wid*16, acc);
        __syncthreads();                      // agg tile dead
        float* sOut = (float*)(sm + R_H);
        stage_frags8(sOut, wid*16, lane, acc);
        __syncthreads();
        if (tid < 128) ln_pack_row(sOut, node0 + tid, tid, nullptr, lg1, lb1, Xhi, Xlo);
        __syncthreads();
    }

    // phase 2: interleaved FFN1 halves + FFN2 K-chunks; hid stays in smem
    float acc2[8][4]; zero8(acc2);
#pragma unroll
    for (int h = 0; h < 2; h++){
        stage_B<H>(W1 + h*64, 2*H, Bhi, Blo, tid);     // W1 cols h*64..h*64+63
        __syncthreads();
        float acc1[8][4]; zero8(acc1);
        mma_loop<4>(Xhi, Xlo, Bhi, Blo, lane, wid*16, acc1);
        __syncthreads();                               // B dead, H dead (prev chunk read)
        frag_relu_pack(Hhi, Hlo, wid*16, lane, acc1, b1 + h*64);
        stage_B<H>(W2 + h*64*64, 64, Bhi, Blo, tid);   // W2 rows h*64..h*64+63
        __syncthreads();                               // hid + B visible
        mma_loop<4>(Hhi, Hlo, Bhi, Blo, lane, wid*16, acc2);
        __syncthreads();                               // before next-iter overwrites
    }
    // phase 3: x = LN2(x + h@W2 + b2)
    {
        float* sOut = (float*)(sm + R_H);
        stage_frags8(sOut, wid*16, lane, acc2);
        __syncthreads();
        if (tid < 128) ln_pack_row(sOut, node0 + tid, tid, b2, lg2, lb2, Xhi, Xlo);
    }
    // phase 4: qkv for next layer
    if (!last)
        qkv_from_x(Xhi, Xlo, Bhi, Blo, Wqn, Wkn, Wvn, node0, wid, lane, tid);
}

// ---------------- warp-per-node attention (online softmax) ----------------
__global__ __launch_bounds__(256) void k_attn(){
    int warp = (blockIdx.x * 256 + threadIdx.x) >> 5;
    int lane = threadIdx.x & 31;
    if (warp >= TOTN) return;
    int node = warp;
    float2 q = *(const float2*)(g_q + (size_t)node * H + 2*lane);
    int s0 = g_rowptr[node], s1 = g_rowptr[node + 1];
    float m = -1e30f, den = 0.f, ax = 0.f, ay = 0.f;
    for (int e = s0; e < s1; e++){
        int src = g_srcs[e];
        float2 kk = *(const float2*)(g_k + (size_t)src * H + 2*lane);
        float2 vv = *(const float2*)(g_v + (size_t)src * H + 2*lane);
        float p = q.x * kk.x + q.y * kk.y;
        p += __shfl_xor_sync(0xffffffffu, p, 1);
        p += __shfl_xor_sync(0xffffffffu, p, 2);
        p += __shfl_xor_sync(0xffffffffu, p, 4);
        float s = p * 0.25f;
        float mn = fmaxf(m, s);
        float scale = __expf(m - mn);
        float w = __expf(s - mn);
        den = den * scale + w;
        ax = ax * scale + w * vv.x;
        ay = ay * scale + w * vv.y;
        m = mn;
    }
    float inv = 1.f / (den + 1e-9f);
    *(float2*)(g_agg + (size_t)node * H + 2*lane) = make_float2(ax * inv, ay * inv);
}

// ---------------- readout + heads ----------------
__global__ void k_gat(const int* __restrict__ an, const float* __restrict__ Wr,
                      const float* __restrict__ br){
    __shared__ float sW[H*ACT];
    __shared__ float sb[ACT];
    int tid = threadIdx.x;
    for (int i = tid; i < H*ACT; i += 128) sW[i] = Wr[i];
    if (tid < ACT) sb[tid] = br[tid];
    __syncthreads();
    int b = tid;
    int node = an[b];
    float acc[ACT];
#pragma unroll
    for (int j = 0; j < ACT; j++) acc[j] = sb[j];
    for (int i = 0; i < H; i++){
        float xi = g_x[(size_t)node * H + i];
#pragma unroll
        for (int j = 0; j < ACT; j++) acc[j] += xi * sW[i*ACT + j];
    }
#pragma unroll
    for (int j = 0; j < ACT; j++) g_gat[b*ACT + j] = acc[j];
}

__global__ __launch_bounds__(512) void k_policy1(const float* __restrict__ obs,
                                                 const float* __restrict__ Wp1,
                                                 const float* __restrict__ bp1){
    __shared__ float sr[ACT + OBSD];
    int b = blockIdx.x;
    for (int i = threadIdx.x; i < ACT; i += 512) sr[i] = g_gat[b*ACT + i];
    for (int i = threadIdx.x; i < OBSD; i += 512) sr[ACT + i] = obs[(size_t)b*OBSD + i];
    __syncthreads();
    int j = threadIdx.x;
    const float* W = Wp1 + j;
    float a0 = 0, a1 = 0, a2 = 0, a3 = 0;
    int i = 0;
    const int K = ACT + OBSD;
    for (; i + 3 < K; i += 4){
        a0 += sr[i+0] * W[(size_t)(i+0)*HS];
        a1 += sr[i+1] * W[(size_t)(i+1)*HS];
        a2 += sr[i+2] * W[(size_t)(i+2)*HS];
        a3 += sr[i+3] * W[(size_t)(i+3)*HS];
    }
    for (; i < K; i++) a0 += sr[i] * W[(size_t)i*HS];
    g_feat[b*HS + j] = tanhf(a0 + a1 + a2 + a3 + bp1[j]);
}

__global__ __launch_bounds__(512) void k_policy2(const float* __restrict__ Wp2,
                                                 const float* __restrict__ bp2){
    __shared__ float sr[HS];
    int b = blockIdx.x;
    for (int i = threadIdx.x; i < HS; i += 512) sr[i] = g_feat[b*HS + i];
    __syncthreads();
    int j = threadIdx.x;
    const float* W = Wp2 + j;
    float a0 = 0, a1 = 0, a2 = 0, a3 = 0;
    for (int i = 0; i < HS; i += 4){
        a0 += sr[i+0] * W[(size_t)(i+0)*HS];
        a1 += sr[i+1] * W[(size_t)(i+1)*HS];
        a2 += sr[i+2] * W[(size_t)(i+2)*HS];
        a3 += sr[i+3] * W[(size_t)(i+3)*HS];
    }
    g_feat2[b*HS + j] = tanhf(a0 + a1 + a2 + a3 + bp2[j]);
}

__global__ void k_logits(const float* __restrict__ Wlog, const float* __restrict__ blog,
                         float* __restrict__ out){
    int b = blockIdx.x;
    int j = threadIdx.x;
    if (j >= NOUTD) return;
    float acc = blog[j];
    for (int i = 0; i < HS; i++) acc += g_feat2[b*HS + i] * Wlog[i*NOUTD + j];
    out[b*NOUTD + j] = acc;
}

__global__ __launch_bounds__(VHD) void k_value1(const float* __restrict__ obs,
                                                const float* __restrict__ Wv1,
                                                const float* __restrict__ bv1){
    __shared__ float sr[OBSD];
    int b = blockIdx.x;
    for (int i = threadIdx.x; i < OBSD; i += VHD) sr[i] = obs[(size_t)b*OBSD + i];
    __syncthreads();
    int j = threadIdx.x;
    const float* W = Wv1 + j;
    float a0 = 0, a1 = 0, a2 = 0, a3 = 0;
    for (int i = 0; i < OBSD; i += 4){
        a0 += sr[i+0] * W[(size_t)(i+0)*VHD];
        a1 += sr[i+1] * W[(size_t)(i+1)*VHD];
        a2 += sr[i+2] * W[(size_t)(i+2)*VHD];
        a3 += sr[i+3] * W[(size_t)(i+3)*VHD];
    }
    g_vh[b*VHD + j] = tanhf(a0 + a1 + a2 + a3 + bv1[j]);
}

__global__ __launch_bounds__(VHD) void k_value2(const float* __restrict__ Wv2,
                                                const float* __restrict__ bv2){
    __shared__ float sr[VHD];
    int b = blockIdx.x;
    sr[threadIdx.x] = g_vh[b*VHD + threadIdx.x];
    __syncthreads();
    int j = threadIdx.x;
    const float* W = Wv2 + j;
    float a0 = 0, a1 = 0, a2 = 0, a3 = 0;
    for (int i = 0; i < VHD; i += 4){
        a0 += sr[i+0] * W[(i+0)*VHD];
        a1 += sr[i+1] * W[(i+1)*VHD];
        a2 += sr[i+2] * W[(i+2)*VHD];
        a3 += sr[i+3] * W[(i+3)*VHD];
    }
    g_vh2[b*VHD + j] = tanhf(a0 + a1 + a2 + a3 + bv2[j]);
}

__global__ void k_valueout(const float* __restrict__ Wvo, const float* __restrict__ bvo,
                           float* __restrict__ out){
    int b = threadIdx.x;
    float acc = bvo[0];
    for (int i = 0; i < VHD; i++) acc += g_vh2[b*VHD + i] * Wvo[i];
    out[BATCH*NOUTD + b] = acc;
}

// ---------------- launch ----------------
extern "C" void kernel_launch(void* const* d_in, const int* in_sizes, int n_in,
                              void* d_out, int out_size){
    const float* node_feats = (const float*)d_in[0];
    const float* obs        = (const float*)d_in[1];
    const int*   edge_src   = (const int*)  d_in[2];
    const int*   edge_dst   = (const int*)  d_in[3];
    const int*   agent      = (const int*)  d_in[4];
    const float* W_in  = (const float*)d_in[5];
    const float* Wq    = (const float*)d_in[6];
    const float* Wk    = (const float*)d_in[7];
    const float* Wv    = (const float*)d_in[8];
    const float* Wo    = (const float*)d_in[9];
    const float* ln1g  = (const float*)d_in[10];
    const float* ln1b  = (const float*)d_in[11];
    const float* W1    = (const float*)d_in[12];
    const float* b1    = (const float*)d_in[13];
    const float* W2    = (const float*)d_in[14];
    const float* b2    = (const float*)d_in[15];
    const float* ln2g  = (const float*)d_in[16];
    const float* ln2b  = (const float*)d_in[17];
    const float* Wr    = (const float*)d_in[18];
    const float* br    = (const float*)d_in[19];
    const float* Wp1   = (const float*)d_in[20];
    const float* bp1   = (const float*)d_in[21];
    const float* Wp2   = (const float*)d_in[22];
    const float* bp2   = (const float*)d_in[23];
    const float* Wlog  = (const float*)d_in[24];
    const float* blog  = (const float*)d_in[25];
    const float* Wv1   = (const float*)d_in[26];
    const float* bv1   = (const float*)d_in[27];
    const float* Wv2   = (const float*)d_in[28];
    const float* bv2   = (const float*)d_in[29];
    const float* Wvo   = (const float*)d_in[30];
    const float* bvo   = (const float*)d_in[31];
    float* out = (float*)d_out;

    cudaFuncSetAttribute((const void*)k_in_qkv, cudaFuncAttributeMaxDynamicSharedMemorySize, SM_LAYER);
    cudaFuncSetAttribute((const void*)k_layer,  cudaFuncAttributeMaxDynamicSharedMemorySize, SM_LAYER);

    k_zero_deg<<<(TOTN + 255)/256, 256>>>();
    k_hist<<<(NEDGE + 255)/256, 256>>>(edge_dst);
    k_scan<<<1, 1024>>>();
    k_in_qkv<<<NB, NTHR, SM_LAYER>>>(node_feats, W_in, Wq, Wk, Wv);   // capture-slot GEMM
    k_scatter<<<(NEDGE + 255)/256, 256>>>(edge_src, edge_dst);

    for (int l = 0; l < LAYERS; l++){
        k_attn<<<(TOTN*32 + 255)/256, 256>>>();
        int nl = l + 1;
        k_layer<<<NB, NTHR, SM_LAYER>>>(Wo + l*H*H, ln1g + l*H, ln1b + l*H,
                                        W1 + l*H*2*H, b1 + l*2*H,
                                        W2 + l*2*H*H, b2 + l*H,
                                        ln2g + l*H, ln2b + l*H,
                                        Wq + nl*H*H, Wk + nl*H*H, Wv + nl*H*H,
                                        (l == LAYERS-1) ? 1 : 0);
    }

    k_gat<<<1, 128>>>(agent, Wr, br);
    k_policy1<<<BATCH, 512>>>(obs, Wp1, bp1);
    k_policy2<<<BATCH, 512>>>(Wp2, bp2);
    k_logits<<<BATCH, 32>>>(Wlog, blog, out);
    k_value1<<<BATCH, VHD>>>(obs, Wv1, bv1);
    k_value2<<<BATCH, VHD>>>(Wv2, bv2);
    k_valueout<<<1, BATCH>>>(Wvo, bvo, out);
}

// round 10
// speedup vs baseline: 1.5625x; 1.0185x over previous
#include <cuda_runtime.h>
#include <cuda_bf16.h>
#include <cstdint>

// ---------------- problem constants ----------------
#define LAYERS 4
#define NHEADS 4
#define H 64
#define DHD 16
#define FIN 32
#define ACT 15
#define OBSD 1500
#define HS 512
#define NOUTD 15
#define VHD 128
#define BATCH 128
#define NNODE 1000
#define TOTN (BATCH*NNODE)      // 128000
#define DEG 4
#define NEDGE (TOTN*DEG)        // 512000

#define BM 128
#define NB (TOTN/BM)            // 1000
#define NTHR 256                // 8 warps

#define SA64 72                 // bf16-elem stride; 144B%128B=16 -> conflict-free ldmatrix
#define A64_B   (128*SA64*2)    // 18432 per hi/lo component
#define B64_B   (64*SA64*2)     // 9216 per component
#define TILE_B  (2*B64_B)       // 18432: packed hi+lo tile image

// fused-layer smem regions (bytes)
#define R_X   0                  // x hi/lo: 36864
#define R_B   36864              // weight tile hi/lo (contiguous hi then lo): 18432
#define R_H   55296              // agg A / sOut / hid hi/lo: 36864
#define SM_LAYER 92160           // 2 CTAs/SM

#define NTILES 33                // Win + 4 layers x {q,k,v,o,w1a,w1b,w2a,w2b}

// ---------------- scratch ----------------
__device__ __align__(16) float g_x[TOTN*H];
__device__ __align__(16) float g_q[TOTN*H];
__device__ __align__(16) float g_k[TOTN*H];
__device__ __align__(16) float g_v[TOTN*H];
__device__ __align__(16) float g_agg[TOTN*H];
__device__ __align__(16) char g_wimg[NTILES*TILE_B];   // 608KB packed weight image
__device__ int g_deg[TOTN];
__device__ int g_rowptr[TOTN+1];
__device__ int g_cursor[TOTN];
__device__ int g_srcs[NEDGE];
__device__ float g_gat[BATCH*ACT];
__device__ __align__(16) float g_feat[BATCH*HS];
__device__ __align__(16) float g_feat2[BATCH*HS];
__device__ __align__(16) float g_vh[BATCH*VHD];
__device__ __align__(16) float g_vh2[BATCH*VHD];

// ---------------- mma / ldmatrix primitives ----------------
__device__ __forceinline__ uint32_t smem_u32(const void* p){
    uint32_t a;
    asm("{ .reg .u64 t; cvta.to.shared.u64 t, %1; cvt.u32.u64 %0, t; }" : "=r"(a) : "l"(p));
    return a;
}
__device__ __forceinline__ void ldsm4(uint32_t* r, uint32_t addr){
    asm volatile("ldmatrix.sync.aligned.m8n8.x4.shared.b16 {%0,%1,%2,%3}, [%4];"
        : "=r"(r[0]),"=r"(r[1]),"=r"(r[2]),"=r"(r[3]) : "r"(addr));
}
__device__ __forceinline__ void mma4(float* c, const uint32_t* a, uint32_t b0, uint32_t b1){
    asm volatile("mma.sync.aligned.m16n8k16.row.col.f32.bf16.bf16.f32 "
        "{%0,%1,%2,%3}, {%4,%5,%6,%7}, {%8,%9}, {%0,%1,%2,%3};"
        : "+f"(c[0]),"+f"(c[1]),"+f"(c[2]),"+f"(c[3])
        : "r"(a[0]),"r"(a[1]),"r"(a[2]),"r"(a[3]), "r"(b0),"r"(b1));
}
__device__ __forceinline__ void pack2(float v0, float v1, uint32_t& hp, uint32_t& lp){
    __nv_bfloat16 h0 = __float2bfloat16(v0), h1 = __float2bfloat16(v1);
    float r0 = v0 - __bfloat162float(h0), r1 = v1 - __bfloat162float(h1);
    __nv_bfloat16 l0 = __float2bfloat16(r0), l1 = __float2bfloat16(r1);
    hp = ((uint32_t)__bfloat16_as_ushort(h1) << 16) | __bfloat16_as_ushort(h0);
    lp = ((uint32_t)__bfloat16_as_ushort(l1) << 16) | __bfloat16_as_ushort(l0);
}

// stage 128xKC fp32 (row stride rs) -> hi/lo bf16 smem at SA64
template<int KC>
__device__ __forceinline__ void stage_A(const float* __restrict__ g, int rs,
                                        char* hi, char* lo, int tid){
    for (int idx = tid; idx < 128*(KC/8); idx += NTHR){
        int row = idx / (KC/8), c8 = (idx % (KC/8)) * 8;
        float4 f0 = *(const float4*)(g + (size_t)row*rs + c8);
        float4 f1 = *(const float4*)(g + (size_t)row*rs + c8 + 4);
        float v[8] = {f0.x,f0.y,f0.z,f0.w,f1.x,f1.y,f1.z,f1.w};
        uint32_t hp[4], lp[4];
#pragma unroll
        for (int j = 0; j < 4; j++) pack2(v[2*j], v[2*j+1], hp[j], lp[j]);
        *(uint4*)(hi + row*SA64*2 + c8*2) = make_uint4(hp[0],hp[1],hp[2],hp[3]);
        *(uint4*)(lo + row*SA64*2 + c8*2) = make_uint4(lp[0],lp[1],lp[2],lp[3]);
    }
}
// coalesced copy of a pre-packed weight tile (hi+lo contiguous) into smem B region
__device__ __forceinline__ void stage_Bimg(int tile, char* Bhi, int tid){
    const uint4* s = (const uint4*)(g_wimg + (size_t)tile * TILE_B);
    uint4* d = (uint4*)Bhi;
    for (int i = tid; i < TILE_B/16; i += NTHR) d[i] = s[i];
}

// warp mma: 16 rows x 64 cols, KS k16-steps, hi/lo 3-term
template<int KS>
__device__ __forceinline__ void mma_loop(const char* A_hi, const char* A_lo,
                                         const char* B_hi, const char* B_lo,
                                         int lane, int m0, float acc[][4]){
    int q = lane >> 3, r = lane & 7;
    uint32_t aoff = (uint32_t)(m0 + ((q & 1) << 3) + r) * (SA64*2) + (((q >> 1) << 3) * 2);
    uint32_t ah = smem_u32(A_hi) + aoff, al = smem_u32(A_lo) + aoff;
    uint32_t boff = (uint32_t)(((q >> 1) << 3) + r) * (SA64*2) + (((q & 1) << 3) * 2);
    uint32_t bh0 = smem_u32(B_hi) + boff, bl0 = smem_u32(B_lo) + boff;
#pragma unroll
    for (int kk = 0; kk < KS; kk++){
        uint32_t af[4], alf[4];
        ldsm4(af,  ah + kk*32);
        ldsm4(alf, al + kk*32);
#pragma unroll
        for (int g2 = 0; g2 < 4; g2++){
            uint32_t bf[4], blf[4];
            ldsm4(bf,  bh0 + g2*16*(SA64*2) + kk*32);
            ldsm4(blf, bl0 + g2*16*(SA64*2) + kk*32);
            mma4(acc[g2*2],   af,  bf[0],  bf[1]);
            mma4(acc[g2*2+1], af,  bf[2],  bf[3]);
            mma4(acc[g2*2],   af,  blf[0], blf[1]);
            mma4(acc[g2*2+1], af,  blf[2], blf[3]);
            mma4(acc[g2*2],   alf, bf[0],  bf[1]);
            mma4(acc[g2*2+1], alf, bf[2],  bf[3]);
        }
    }
}
__device__ __forceinline__ void zero8(float acc[][4]){
#pragma unroll
    for (int i = 0; i < 8; i++){ acc[i][0]=0; acc[i][1]=0; acc[i][2]=0; acc[i][3]=0; }
}
__device__ __forceinline__ void store_frags8(float* __restrict__ g, int rs, int m0,
                                             int lane, float acc[][4]){
    int r = lane >> 2, c2 = (lane & 3) * 2;
#pragma unroll
    for (int nt = 0; nt < 8; nt++){
        int col = nt*8 + c2;
        *(float2*)(g + (size_t)(m0+r)*rs + col)   = make_float2(acc[nt][0], acc[nt][1]);
        *(float2*)(g + (size_t)(m0+r+8)*rs + col) = make_float2(acc[nt][2], acc[nt][3]);
    }
}
__device__ __forceinline__ void stage_frags8(float* sOut, int m0, int lane, float acc[][4]){
    int r = lane >> 2, c2 = (lane & 3) * 2;
#pragma unroll
    for (int nt = 0; nt < 8; nt++){
        int col = nt*8 + c2;
        *(float2*)(sOut + (m0+r)*66 + col)   = make_float2(acc[nt][0], acc[nt][1]);
        *(float2*)(sOut + (m0+r+8)*66 + col) = make_float2(acc[nt][2], acc[nt][3]);
    }
}
// relu(acc+bias) frags -> hid hi/lo smem
__device__ __forceinline__ void frag_relu_pack(char* Hhi, char* Hlo, int m0, int lane,
                                               float acc[][4], const float* __restrict__ bias){
    int r = lane >> 2, c2 = (lane & 3) * 2;
#pragma unroll
    for (int nt = 0; nt < 8; nt++){
        int col = nt*8 + c2;
        float b0 = __ldg(bias+col), b1 = __ldg(bias+col+1);
        float v0 = fmaxf(acc[nt][0]+b0, 0.f), v1 = fmaxf(acc[nt][1]+b1, 0.f);
        float v2 = fmaxf(acc[nt][2]+b0, 0.f), v3 = fmaxf(acc[nt][3]+b1, 0.f);
        uint32_t hp, lp;
        pack2(v0, v1, hp, lp);
        *(uint32_t*)(Hhi + (m0+r)*SA64*2 + col*2) = hp;
        *(uint32_t*)(Hlo + (m0+r)*SA64*2 + col*2) = lp;
        pack2(v2, v3, hp, lp);
        *(uint32_t*)(Hhi + (m0+r+8)*SA64*2 + col*2) = hp;
        *(uint32_t*)(Hlo + (m0+r+8)*SA64*2 + col*2) = lp;
    }
}
// LN(+residual,+bias) from sOut row -> g_x fp32 AND hi/lo pack into X region
__device__ __forceinline__ void ln_pack_row(const float* sOut, int node, int row,
                                            const float* __restrict__ bias,
                                            const float* __restrict__ lg,
                                            const float* __restrict__ lb,
                                            char* Xhi, char* Xlo){
    float o[H];
#pragma unroll
    for (int i = 0; i < H; i++) o[i] = sOut[row*66 + i];
    const float4* xp = (const float4*)(g_x + (size_t)node * H);
#pragma unroll
    for (int i = 0; i < 16; i++){
        float4 f = xp[i];
        o[4*i+0] += f.x; o[4*i+1] += f.y; o[4*i+2] += f.z; o[4*i+3] += f.w;
    }
    if (bias){
#pragma unroll
        for (int i = 0; i < H; i++) o[i] += __ldg(&bias[i]);
    }
    float mean = 0.f;
#pragma unroll
    for (int i = 0; i < H; i++) mean += o[i];
    mean *= (1.f / H);
    float var = 0.f;
#pragma unroll
    for (int i = 0; i < H; i++){ float d = o[i] - mean; var += d * d; }
    var *= (1.f / H);
    float rr = rsqrtf(var + 1e-5f);
    float g[H];
#pragma unroll
    for (int i = 0; i < H; i++)
        g[i] = (o[i]-mean)*rr*__ldg(&lg[i]) + __ldg(&lb[i]);
    float4* op = (float4*)(g_x + (size_t)node * H);
#pragma unroll
    for (int i = 0; i < 16; i++)
        op[i] = make_float4(g[4*i+0], g[4*i+1], g[4*i+2], g[4*i+3]);
#pragma unroll
    for (int i = 0; i < 32; i++){
        uint32_t hp, lp;
        pack2(g[2*i], g[2*i+1], hp, lp);
        *(uint32_t*)(Xhi + row*SA64*2 + i*4) = hp;
        *(uint32_t*)(Xlo + row*SA64*2 + i*4) = lp;
    }
}
// plain row (no LN) -> g_x + pack
__device__ __forceinline__ void row_store_pack(const float* sOut, int node, int row,
                                               char* Xhi, char* Xlo){
    float g[H];
#pragma unroll
    for (int i = 0; i < H; i++) g[i] = sOut[row*66 + i];
    float4* op = (float4*)(g_x + (size_t)node * H);
#pragma unroll
    for (int i = 0; i < 16; i++)
        op[i] = make_float4(g[4*i+0], g[4*i+1], g[4*i+2], g[4*i+3]);
#pragma unroll
    for (int i = 0; i < 32; i++){
        uint32_t hp, lp;
        pack2(g[2*i], g[2*i+1], hp, lp);
        *(uint32_t*)(Xhi + row*SA64*2 + i*4) = hp;
        *(uint32_t*)(Xlo + row*SA64*2 + i*4) = lp;
    }
}
// qkv from packed X via packed tiles t0..t0+2
__device__ __forceinline__ void qkv_from_x(char* Xhi, char* Xlo, char* Bhi, char* Blo,
                                           int t0, int node0, int wid, int lane, int tid){
    float* outs[3] = { g_q, g_k, g_v };
#pragma unroll
    for (int m = 0; m < 3; m++){
        __syncthreads();                 // prev B readers done / X pack visible
        stage_Bimg(t0 + m, Bhi, tid);
        __syncthreads();
        float acc[8][4]; zero8(acc);
        mma_loop<4>(Xhi, Xlo, Bhi, Blo, lane, wid*16, acc);
        store_frags8(outs[m] + (size_t)node0 * H, H, wid*16, lane, acc);
    }
}

// ---------------- weight prep: pack all tiles once ----------------
__global__ void k_prep(const float* __restrict__ Win, const float* __restrict__ Wq,
                       const float* __restrict__ Wk, const float* __restrict__ Wv,
                       const float* __restrict__ Wo, const float* __restrict__ W1,
                       const float* __restrict__ W2){
    int t = blockIdx.x;
    const float* src; int ns, Ksrc;
    if (t == 0){ src = Win; ns = 64; Ksrc = FIN; }
    else {
        int l = (t-1)/8, j = (t-1)%8;
        if (j < 3){ const float* ws[3] = {Wq,Wk,Wv}; src = ws[j] + l*H*H; ns = 64; Ksrc = 64; }
        else if (j == 3){ src = Wo + l*H*H; ns = 64; Ksrc = 64; }
        else if (j < 6){ src = W1 + l*H*2*H + (j-4)*64; ns = 128; Ksrc = 64; }
        else { src = W2 + l*2*H*H + (j-6)*64*64; ns = 64; Ksrc = 64; }
    }
    char* dst = g_wimg + (size_t)t * TILE_B;
    for (int idx = threadIdx.x; idx < 64*32; idx += 256){
        int n = idx >> 5, p = idx & 31, k = 2*p;
        float v0 = (k   < Ksrc) ? __ldg(src + (size_t)k*ns + n)     : 0.f;
        float v1 = (k+1 < Ksrc) ? __ldg(src + (size_t)(k+1)*ns + n) : 0.f;
        uint32_t hp, lp;
        pack2(v0, v1, hp, lp);
        *(uint32_t*)(dst + n*SA64*2 + k*2) = hp;
        *(uint32_t*)(dst + B64_B + n*SA64*2 + k*2) = lp;
    }
}

// ---------------- CSR build ----------------
__global__ void k_zero_deg(){
    int i = blockIdx.x * 256 + threadIdx.x;
    if (i < TOTN) g_deg[i] = 0;
}
__global__ void k_hist(const int* __restrict__ edst){
    int e = blockIdx.x * 256 + threadIdx.x;
    if (e < NEDGE) atomicAdd(&g_deg[edst[e]], 1);
}
__global__ void k_scan(){
    __shared__ int ssum[1024];
    int t = threadIdx.x;
    int base = t * 125;
    int s = 0;
    for (int i = 0; i < 125; i++) s += g_deg[base + i];
    ssum[t] = s;
    __syncthreads();
    if (t == 0){
        int run = 0;
        for (int i = 0; i < 1024; i++){ int v = ssum[i]; ssum[i] = run; run += v; }
    }
    __syncthreads();
    int run = ssum[t];
    for (int i = 0; i < 125; i++){
        g_rowptr[base + i] = run;
        g_cursor[base + i] = run;
        run += g_deg[base + i];
    }
    if (t == 1023) g_rowptr[TOTN] = run;
}
__global__ void k_scatter(const int* __restrict__ esrc, const int* __restrict__ edst){
    int e = blockIdx.x * 256 + threadIdx.x;
    if (e < NEDGE){
        int d = edst[e];
        int pos = atomicAdd(&g_cursor[d], 1);
        g_srcs[pos] = esrc[e];
    }
}

// ---------------- fused input + layer-0 qkv ----------------
__global__ __launch_bounds__(NTHR) void k_in_qkv(const float* __restrict__ nf){
    extern __shared__ __align__(16) char sm[];
    char* Xhi = sm + R_X;  char* Xlo = Xhi + A64_B;
    char* Bhi = sm + R_B;  char* Blo = Bhi + B64_B;
    char* Hhi = sm + R_H;  char* Hlo = Hhi + A64_B;
    int tid = threadIdx.x, wid = tid >> 5, lane = tid & 31;
    int node0 = blockIdx.x * BM;

    stage_A<FIN>(nf + (size_t)node0 * FIN, FIN, Hhi, Hlo, tid);
    stage_Bimg(0, Bhi, tid);
    __syncthreads();
    float acc[8][4]; zero8(acc);
    mma_loop<2>(Hhi, Hlo, Bhi, Blo, lane, wid*16, acc);
    __syncthreads();
    float* sOut = (float*)(sm + R_H);
    stage_frags8(sOut, wid*16, lane, acc);
    __syncthreads();
    if (tid < 128) row_store_pack(sOut, node0 + tid, tid, Xhi, Xlo);

    qkv_from_x(Xhi, Xlo, Bhi, Blo, 1, node0, wid, lane, tid);   // layer-0 tiles 1..3
}

// ---------------- fused layer: Wo+LN1+FFN1+FFN2+LN2 (+next qkv) ----------------
__global__ __launch_bounds__(NTHR) void k_layer(int l,
                                                const float* __restrict__ lg1,
                                                const float* __restrict__ lb1,
                                                const float* __restrict__ b1,
                                                const float* __restrict__ b2,
                                                const float* __restrict__ lg2,
                                                const float* __restrict__ lb2,
                                                int last){
    extern __shared__ __align__(16) char sm[];
    char* Xhi = sm + R_X;  char* Xlo = Xhi + A64_B;
    char* Bhi = sm + R_B;  char* Blo = Bhi + B64_B;
    char* Hhi = sm + R_H;  char* Hlo = Hhi + A64_B;
    int tid = threadIdx.x, wid = tid >> 5, lane = tid & 31;
    int node0 = blockIdx.x * BM;
    int tb = 1 + l*8;   // tile base for this layer

    // phase 1: attn_out = agg @ Wo ; x = LN1(x + attn_out)
    stage_A<H>(g_agg + (size_t)node0 * H, H, Hhi, Hlo, tid);
    stage_Bimg(tb + 3, Bhi, tid);
    __syncthreads();
    {
        float acc[8][4]; zero8(acc);
        mma_loop<4>(Hhi, Hlo, Bhi, Blo, lane, wid*16, acc);
        __syncthreads();
        float* sOut = (float*)(sm + R_H);
        stage_frags8(sOut, wid*16, lane, acc);
        __syncthreads();
        if (tid < 128) ln_pack_row(sOut, node0 + tid, tid, nullptr, lg1, lb1, Xhi, Xlo);
        __syncthreads();
    }

    // phase 2: interleaved FFN1 halves + FFN2 K-chunks; hid stays in smem
    float acc2[8][4]; zero8(acc2);
#pragma unroll
    for (int h = 0; h < 2; h++){
        stage_Bimg(tb + 4 + h, Bhi, tid);          // W1 half h
        __syncthreads();
        float acc1[8][4]; zero8(acc1);
        mma_loop<4>(Xhi, Xlo, Bhi, Blo, lane, wid*16, acc1);
        __syncthreads();
        frag_relu_pack(Hhi, Hlo, wid*16, lane, acc1, b1 + h*64);
        stage_Bimg(tb + 6 + h, Bhi, tid);          // W2 chunk h
        __syncthreads();
        mma_loop<4>(Hhi, Hlo, Bhi, Blo, lane, wid*16, acc2);
        __syncthreads();
    }
    // phase 3: x = LN2(x + h@W2 + b2)
    {
        float* sOut = (float*)(sm + R_H);
        stage_frags8(sOut, wid*16, lane, acc2);
        __syncthreads();
        if (tid < 128) ln_pack_row(sOut, node0 + tid, tid, b2, lg2, lb2, Xhi, Xlo);
    }
    // phase 4: qkv for next layer
    if (!last)
        qkv_from_x(Xhi, Xlo, Bhi, Blo, tb + 8, node0, wid, lane, tid);
}

// ---------------- warp-per-node attention (online softmax) ----------------
__global__ __launch_bounds__(256) void k_attn(){
    int warp = (blockIdx.x * 256 + threadIdx.x) >> 5;
    int lane = threadIdx.x & 31;
    if (warp >= TOTN) return;
    int node = warp;
    float2 q = *(const float2*)(g_q + (size_t)node * H + 2*lane);
    int s0 = g_rowptr[node], s1 = g_rowptr[node + 1];
    float m = -1e30f, den = 0.f, ax = 0.f, ay = 0.f;
    for (int e = s0; e < s1; e++){
        int src = g_srcs[e];
        float2 kk = *(const float2*)(g_k + (size_t)src * H + 2*lane);
        float2 vv = *(const float2*)(g_v + (size_t)src * H + 2*lane);
        float p = q.x * kk.x + q.y * kk.y;
        p += __shfl_xor_sync(0xffffffffu, p, 1);
        p += __shfl_xor_sync(0xffffffffu, p, 2);
        p += __shfl_xor_sync(0xffffffffu, p, 4);
        float s = p * 0.25f;
        float mn = fmaxf(m, s);
        float scale = __expf(m - mn);
        float w = __expf(s - mn);
        den = den * scale + w;
        ax = ax * scale + w * vv.x;
        ay = ay * scale + w * vv.y;
        m = mn;
    }
    float inv = 1.f / (den + 1e-9f);
    *(float2*)(g_agg + (size_t)node * H + 2*lane) = make_float2(ax * inv, ay * inv);
}

// ---------------- readout + heads ----------------
__global__ void k_gat(const int* __restrict__ an, const float* __restrict__ Wr,
                      const float* __restrict__ br){
    __shared__ float sW[H*ACT];
    __shared__ float sb[ACT];
    int tid = threadIdx.x;
    for (int i = tid; i < H*ACT; i += 128) sW[i] = Wr[i];
    if (tid < ACT) sb[tid] = br[tid];
    __syncthreads();
    int b = tid;
    int node = an[b];
    float acc[ACT];
#pragma unroll
    for (int j = 0; j < ACT; j++) acc[j] = sb[j];
    for (int i = 0; i < H; i++){
        float xi = g_x[(size_t)node * H + i];
#pragma unroll
        for (int j = 0; j < ACT; j++) acc[j] += xi * sW[i*ACT + j];
    }
#pragma unroll
    for (int j = 0; j < ACT; j++) g_gat[b*ACT + j] = acc[j];
}

__global__ __launch_bounds__(512) void k_policy1(const float* __restrict__ obs,
                                                 const float* __restrict__ Wp1,
                                                 const float* __restrict__ bp1){
    __shared__ float sr[ACT + OBSD];
    int b = blockIdx.x;
    for (int i = threadIdx.x; i < ACT; i += 512) sr[i] = g_gat[b*ACT + i];
    for (int i = threadIdx.x; i < OBSD; i += 512) sr[ACT + i] = obs[(size_t)b*OBSD + i];
    __syncthreads();
    int j = threadIdx.x;
    const float* W = Wp1 + j;
    float a0 = 0, a1 = 0, a2 = 0, a3 = 0;
    int i = 0;
    const int K = ACT + OBSD;
    for (; i + 3 < K; i += 4){
        a0 += sr[i+0] * W[(size_t)(i+0)*HS];
        a1 += sr[i+1] * W[(size_t)(i+1)*HS];
        a2 += sr[i+2] * W[(size_t)(i+2)*HS];
        a3 += sr[i+3] * W[(size_t)(i+3)*HS];
    }
    for (; i < K; i++) a0 += sr[i] * W[(size_t)i*HS];
    g_feat[b*HS + j] = tanhf(a0 + a1 + a2 + a3 + bp1[j]);
}

__global__ __launch_bounds__(512) void k_policy2(const float* __restrict__ Wp2,
                                                 const float* __restrict__ bp2){
    __shared__ float sr[HS];
    int b = blockIdx.x;
    for (int i = threadIdx.x; i < HS; i += 512) sr[i] = g_feat[b*HS + i];
    __syncthreads();
    int j = threadIdx.x;
    const float* W = Wp2 + j;
    float a0 = 0, a1 = 0, a2 = 0, a3 = 0;
    for (int i = 0; i < HS; i += 4){
        a0 += sr[i+0] * W[(size_t)(i+0)*HS];
        a1 += sr[i+1] * W[(size_t)(i+1)*HS];
        a2 += sr[i+2] * W[(size_t)(i+2)*HS];
        a3 += sr[i+3] * W[(size_t)(i+3)*HS];
    }
    g_feat2[b*HS + j] = tanhf(a0 + a1 + a2 + a3 + bp2[j]);
}

__global__ void k_logits(const float* __restrict__ Wlog, const float* __restrict__ blog,
                         float* __restrict__ out){
    int b = blockIdx.x;
    int j = threadIdx.x;
    if (j >= NOUTD) return;
    float acc = blog[j];
    for (int i = 0; i < HS; i++) acc += g_feat2[b*HS + i] * Wlog[i*NOUTD + j];
    out[b*NOUTD + j] = acc;
}

__global__ __launch_bounds__(VHD) void k_value1(const float* __restrict__ obs,
                                                const float* __restrict__ Wv1,
                                                const float* __restrict__ bv1){
    __shared__ float sr[OBSD];
    int b = blockIdx.x;
    for (int i = threadIdx.x; i < OBSD; i += VHD) sr[i] = obs[(size_t)b*OBSD + i];
    __syncthreads();
    int j = threadIdx.x;
    const float* W = Wv1 + j;
    float a0 = 0, a1 = 0, a2 = 0, a3 = 0;
    for (int i = 0; i < OBSD; i += 4){
        a0 += sr[i+0] * W[(size_t)(i+0)*VHD];
        a1 += sr[i+1] * W[(size_t)(i+1)*VHD];
        a2 += sr[i+2] * W[(size_t)(i+2)*VHD];
        a3 += sr[i+3] * W[(size_t)(i+3)*VHD];
    }
    g_vh[b*VHD + j] = tanhf(a0 + a1 + a2 + a3 + bv1[j]);
}

__global__ __launch_bounds__(VHD) void k_value2(const float* __restrict__ Wv2,
                                                const float* __restrict__ bv2){
    __shared__ float sr[VHD];
    int b = blockIdx.x;
    sr[threadIdx.x] = g_vh[b*VHD + threadIdx.x];
    __syncthreads();
    int j = threadIdx.x;
    const float* W = Wv2 + j;
    float a0 = 0, a1 = 0, a2 = 0, a3 = 0;
    for (int i = 0; i < VHD; i += 4){
        a0 += sr[i+0] * W[(i+0)*VHD];
        a1 += sr[i+1] * W[(i+1)*VHD];
        a2 += sr[i+2] * W[(i+2)*VHD];
        a3 += sr[i+3] * W[(i+3)*VHD];
    }
    g_vh2[b*VHD + j] = tanhf(a0 + a1 + a2 + a3 + bv2[j]);
}

__global__ void k_valueout(const float* __restrict__ Wvo, const float* __restrict__ bvo,
                           float* __restrict__ out){
    int b = threadIdx.x;
    float acc = bvo[0];
    for (int i = 0; i < VHD; i++) acc += g_vh2[b*VHD + i] * Wvo[i];
    out[BATCH*NOUTD + b] = acc;
}

// ---------------- launch ----------------
extern "C" void kernel_launch(void* const* d_in, const int* in_sizes, int n_in,
                              void* d_out, int out_size){
    const float* node_feats = (const float*)d_in[0];
    const float* obs        = (const float*)d_in[1];
    const int*   edge_src   = (const int*)  d_in[2];
    const int*   edge_dst   = (const int*)  d_in[3];
    const int*   agent      = (const int*)  d_in[4];
    const float* W_in  = (const float*)d_in[5];
    const float* Wq    = (const float*)d_in[6];
    const float* Wk    = (const float*)d_in[7];
    const float* Wv    = (const float*)d_in[8];
    const float* Wo    = (const float*)d_in[9];
    const float* ln1g  = (const float*)d_in[10];
    const float* ln1b  = (const float*)d_in[11];
    const float* W1    = (const float*)d_in[12];
    const float* b1    = (const float*)d_in[13];
    const float* W2    = (const float*)d_in[14];
    const float* b2    = (const float*)d_in[15];
    const float* ln2g  = (const float*)d_in[16];
    const float* ln2b  = (const float*)d_in[17];
    const float* Wr    = (const float*)d_in[18];
    const float* br    = (const float*)d_in[19];
    const float* Wp1   = (const float*)d_in[20];
    const float* bp1   = (const float*)d_in[21];
    const float* Wp2   = (const float*)d_in[22];
    const float* bp2   = (const float*)d_in[23];
    const float* Wlog  = (const float*)d_in[24];
    const float* blog  = (const float*)d_in[25];
    const float* Wv1   = (const float*)d_in[26];
    const float* bv1   = (const float*)d_in[27];
    const float* Wv2   = (const float*)d_in[28];
    const float* bv2   = (const float*)d_in[29];
    const float* Wvo   = (const float*)d_in[30];
    const float* bvo   = (const float*)d_in[31];
    float* out = (float*)d_out;

    cudaFuncSetAttribute((const void*)k_in_qkv, cudaFuncAttributeMaxDynamicSharedMemorySize, SM_LAYER);
    cudaFuncSetAttribute((const void*)k_layer,  cudaFuncAttributeMaxDynamicSharedMemorySize, SM_LAYER);

    k_prep<<<NTILES, 256>>>(W_in, Wq, Wk, Wv, Wo, W1, W2);
    k_zero_deg<<<(TOTN + 255)/256, 256>>>();
    k_hist<<<(NEDGE + 255)/256, 256>>>(edge_dst);
    k_scan<<<1, 1024>>>();
    k_in_qkv<<<NB, NTHR, SM_LAYER>>>(node_feats);
    k_scatter<<<(NEDGE + 255)/256, 256>>>(edge_src, edge_dst);

    for (int l = 0; l < LAYERS; l++){
        k_attn<<<(TOTN*32 + 255)/256, 256>>>();
        k_layer<<<NB, NTHR, SM_LAYER>>>(l, ln1g + l*H, ln1b + l*H,
                                        b1 + l*2*H, b2 + l*H,
                                        ln2g + l*H, ln2b + l*H,
                                        (l == LAYERS-1) ? 1 : 0);
    }

    k_gat<<<1, 128>>>(agent, Wr, br);
    k_policy1<<<BATCH, 512>>>(obs, Wp1, bp1);
    k_policy2<<<BATCH, 512>>>(Wp2, bp2);
    k_logits<<<BATCH, 32>>>(Wlog, blog, out);
    k_value1<<<BATCH, VHD>>>(obs, Wv1, bv1);
    k_value2<<<BATCH, VHD>>>(Wv2, bv2);
    k_valueout<<<1, BATCH>>>(Wvo, bvo, out);
}

// round 11
// speedup vs baseline: 1.8038x; 1.1544x over previous
#include <cuda_runtime.h>
#include <cuda_bf16.h>
#include <cstdint>

// ---------------- problem constants ----------------
#define LAYERS 4
#define NHEADS 4
#define H 64
#define DHD 16
#define FIN 32
#define ACT 15
#define OBSD 1500
#define HS 512
#define NOUTD 15
#define VHD 128
#define BATCH 128
#define NNODE 1000
#define TOTN (BATCH*NNODE)      // 128000
#define DEG 4
#define NEDGE (TOTN*DEG)        // 512000

#define BM 128
#define NB (TOTN/BM)            // 1000
#define NTHR 256                // 8 warps

#define SA64 72                 // bf16-elem stride; 144B%128B=16 -> conflict-free ldmatrix
#define A64_B   (128*SA64*2)    // 18432 per hi/lo component
#define B64_B   (64*SA64*2)     // 9216 per component
#define TILE_B  (2*B64_B)       // 18432: packed hi+lo tile image

// fused-layer smem regions (bytes)
#define R_X   0                  // x hi/lo: 36864
#define R_B   36864              // weight tile hi/lo (contiguous hi then lo): 18432
#define R_H   55296              // agg A / sOut / hid hi/lo: 36864
#define SM_LAYER 92160           // 2 CTAs/SM

#define NTILES 33                // Win + 4 layers x {q,k,v,o,w1a,w1b,w2a,w2b}
#define SCAN_BLKS 125            // 125 x 1024 = TOTN

// ---------------- scratch ----------------
__device__ __align__(16) float g_x[TOTN*H];
__device__ __align__(16) float g_q[TOTN*H];
__device__ __align__(16) float g_k[TOTN*H];
__device__ __align__(16) float g_v[TOTN*H];
__device__ __align__(16) float g_agg[TOTN*H];
__device__ __align__(16) char g_wimg[NTILES*TILE_B];   // 608KB packed weight image
__device__ int g_deg[TOTN];
__device__ int g_rowptr[TOTN+1];
__device__ int g_cursor[TOTN];
__device__ int g_srcs[NEDGE];
__device__ int g_bsum[SCAN_BLKS];
__device__ int g_boff[SCAN_BLKS];
__device__ float g_gat[BATCH*ACT];
__device__ __align__(16) float g_feat[BATCH*HS];
__device__ __align__(16) float g_feat2[BATCH*HS];
__device__ __align__(16) float g_vh[BATCH*VHD];
__device__ __align__(16) float g_vh2[BATCH*VHD];

// ---------------- mma / ldmatrix primitives ----------------
__device__ __forceinline__ uint32_t smem_u32(const void* p){
    uint32_t a;
    asm("{ .reg .u64 t; cvta.to.shared.u64 t, %1; cvt.u32.u64 %0, t; }" : "=r"(a) : "l"(p));
    return a;
}
__device__ __forceinline__ void ldsm4(uint32_t* r, uint32_t addr){
    asm volatile("ldmatrix.sync.aligned.m8n8.x4.shared.b16 {%0,%1,%2,%3}, [%4];"
        : "=r"(r[0]),"=r"(r[1]),"=r"(r[2]),"=r"(r[3]) : "r"(addr));
}
__device__ __forceinline__ void mma4(float* c, const uint32_t* a, uint32_t b0, uint32_t b1){
    asm volatile("mma.sync.aligned.m16n8k16.row.col.f32.bf16.bf16.f32 "
        "{%0,%1,%2,%3}, {%4,%5,%6,%7}, {%8,%9}, {%0,%1,%2,%3};"
        : "+f"(c[0]),"+f"(c[1]),"+f"(c[2]),"+f"(c[3])
        : "r"(a[0]),"r"(a[1]),"r"(a[2]),"r"(a[3]), "r"(b0),"r"(b1));
}
__device__ __forceinline__ void pack2(float v0, float v1, uint32_t& hp, uint32_t& lp){
    __nv_bfloat16 h0 = __float2bfloat16(v0), h1 = __float2bfloat16(v1);
    float r0 = v0 - __bfloat162float(h0), r1 = v1 - __bfloat162float(h1);
    __nv_bfloat16 l0 = __float2bfloat16(r0), l1 = __float2bfloat16(r1);
    hp = ((uint32_t)__bfloat16_as_ushort(h1) << 16) | __bfloat16_as_ushort(h0);
    lp = ((uint32_t)__bfloat16_as_ushort(l1) << 16) | __bfloat16_as_ushort(l0);
}

// stage 128xKC fp32 (row stride rs) -> hi/lo bf16 smem at SA64
template<int KC>
__device__ __forceinline__ void stage_A(const float* __restrict__ g, int rs,
                                        char* hi, char* lo, int tid){
    for (int idx = tid; idx < 128*(KC/8); idx += NTHR){
        int row = idx / (KC/8), c8 = (idx % (KC/8)) * 8;
        float4 f0 = *(const float4*)(g + (size_t)row*rs + c8);
        float4 f1 = *(const float4*)(g + (size_t)row*rs + c8 + 4);
        float v[8] = {f0.x,f0.y,f0.z,f0.w,f1.x,f1.y,f1.z,f1.w};
        uint32_t hp[4], lp[4];
#pragma unroll
        for (int j = 0; j < 4; j++) pack2(v[2*j], v[2*j+1], hp[j], lp[j]);
        *(uint4*)(hi + row*SA64*2 + c8*2) = make_uint4(hp[0],hp[1],hp[2],hp[3]);
        *(uint4*)(lo + row*SA64*2 + c8*2) = make_uint4(lp[0],lp[1],lp[2],lp[3]);
    }
}
// coalesced copy of a pre-packed weight tile into smem B region
__device__ __forceinline__ void stage_Bimg(int tile, char* Bhi, int tid){
    const uint4* s = (const uint4*)(g_wimg + (size_t)tile * TILE_B);
    uint4* d = (uint4*)Bhi;
    for (int i = tid; i < TILE_B/16; i += NTHR) d[i] = s[i];
}

// warp mma: 16 rows x 64 cols, KS k16-steps, hi/lo 3-term
template<int KS>
__device__ __forceinline__ void mma_loop(const char* A_hi, const char* A_lo,
                                         const char* B_hi, const char* B_lo,
                                         int lane, int m0, float acc[][4]){
    int q = lane >> 3, r = lane & 7;
    uint32_t aoff = (uint32_t)(m0 + ((q & 1) << 3) + r) * (SA64*2) + (((q >> 1) << 3) * 2);
    uint32_t ah = smem_u32(A_hi) + aoff, al = smem_u32(A_lo) + aoff;
    uint32_t boff = (uint32_t)(((q >> 1) << 3) + r) * (SA64*2) + (((q & 1) << 3) * 2);
    uint32_t bh0 = smem_u32(B_hi) + boff, bl0 = smem_u32(B_lo) + boff;
#pragma unroll
    for (int kk = 0; kk < KS; kk++){
        uint32_t af[4], alf[4];
        ldsm4(af,  ah + kk*32);
        ldsm4(alf, al + kk*32);
#pragma unroll
        for (int g2 = 0; g2 < 4; g2++){
            uint32_t bf[4], blf[4];
            ldsm4(bf,  bh0 + g2*16*(SA64*2) + kk*32);
            ldsm4(blf, bl0 + g2*16*(SA64*2) + kk*32);
            mma4(acc[g2*2],   af,  bf[0],  bf[1]);
            mma4(acc[g2*2+1], af,  bf[2],  bf[3]);
            mma4(acc[g2*2],   af,  blf[0], blf[1]);
            mma4(acc[g2*2+1], af,  blf[2], blf[3]);
            mma4(acc[g2*2],   alf, bf[0],  bf[1]);
            mma4(acc[g2*2+1], alf, bf[2],  bf[3]);
        }
    }
}
__device__ __forceinline__ void zero8(float acc[][4]){
#pragma unroll
    for (int i = 0; i < 8; i++){ acc[i][0]=0; acc[i][1]=0; acc[i][2]=0; acc[i][3]=0; }
}
__device__ __forceinline__ void store_frags8(float* __restrict__ g, int rs, int m0,
                                             int lane, float acc[][4]){
    int r = lane >> 2, c2 = (lane & 3) * 2;
#pragma unroll
    for (int nt = 0; nt < 8; nt++){
        int col = nt*8 + c2;
        *(float2*)(g + (size_t)(m0+r)*rs + col)   = make_float2(acc[nt][0], acc[nt][1]);
        *(float2*)(g + (size_t)(m0+r+8)*rs + col) = make_float2(acc[nt][2], acc[nt][3]);
    }
}
__device__ __forceinline__ void stage_frags8(float* sOut, int m0, int lane, float acc[][4]){
    int r = lane >> 2, c2 = (lane & 3) * 2;
#pragma unroll
    for (int nt = 0; nt < 8; nt++){
        int col = nt*8 + c2;
        *(float2*)(sOut + (m0+r)*66 + col)   = make_float2(acc[nt][0], acc[nt][1]);
        *(float2*)(sOut + (m0+r+8)*66 + col) = make_float2(acc[nt][2], acc[nt][3]);
    }
}
// relu(acc+bias) frags -> hid hi/lo smem
__device__ __forceinline__ void frag_relu_pack(char* Hhi, char* Hlo, int m0, int lane,
                                               float acc[][4], const float* __restrict__ bias){
    int r = lane >> 2, c2 = (lane & 3) * 2;
#pragma unroll
    for (int nt = 0; nt < 8; nt++){
        int col = nt*8 + c2;
        float b0 = __ldg(bias+col), b1 = __ldg(bias+col+1);
        float v0 = fmaxf(acc[nt][0]+b0, 0.f), v1 = fmaxf(acc[nt][1]+b1, 0.f);
        float v2 = fmaxf(acc[nt][2]+b0, 0.f), v3 = fmaxf(acc[nt][3]+b1, 0.f);
        uint32_t hp, lp;
        pack2(v0, v1, hp, lp);
        *(uint32_t*)(Hhi + (m0+r)*SA64*2 + col*2) = hp;
        *(uint32_t*)(Hlo + (m0+r)*SA64*2 + col*2) = lp;
        pack2(v2, v3, hp, lp);
        *(uint32_t*)(Hhi + (m0+r+8)*SA64*2 + col*2) = hp;
        *(uint32_t*)(Hlo + (m0+r+8)*SA64*2 + col*2) = lp;
    }
}
// LN(+residual,+bias) from sOut row -> g_x fp32 AND hi/lo pack into X region
__device__ __forceinline__ void ln_pack_row(const float* sOut, int node, int row,
                                            const float* __restrict__ bias,
                                            const float* __restrict__ lg,
                                            const float* __restrict__ lb,
                                            char* Xhi, char* Xlo){
    float o[H];
#pragma unroll
    for (int i = 0; i < H; i++) o[i] = sOut[row*66 + i];
    const float4* xp = (const float4*)(g_x + (size_t)node * H);
#pragma unroll
    for (int i = 0; i < 16; i++){
        float4 f = xp[i];
        o[4*i+0] += f.x; o[4*i+1] += f.y; o[4*i+2] += f.z; o[4*i+3] += f.w;
    }
    if (bias){
#pragma unroll
        for (int i = 0; i < H; i++) o[i] += __ldg(&bias[i]);
    }
    float mean = 0.f;
#pragma unroll
    for (int i = 0; i < H; i++) mean += o[i];
    mean *= (1.f / H);
    float var = 0.f;
#pragma unroll
    for (int i = 0; i < H; i++){ float d = o[i] - mean; var += d * d; }
    var *= (1.f / H);
    float rr = rsqrtf(var + 1e-5f);
    float g[H];
#pragma unroll
    for (int i = 0; i < H; i++)
        g[i] = (o[i]-mean)*rr*__ldg(&lg[i]) + __ldg(&lb[i]);
    float4* op = (float4*)(g_x + (size_t)node * H);
#pragma unroll
    for (int i = 0; i < 16; i++)
        op[i] = make_float4(g[4*i+0], g[4*i+1], g[4*i+2], g[4*i+3]);
#pragma unroll
    for (int i = 0; i < 32; i++){
        uint32_t hp, lp;
        pack2(g[2*i], g[2*i+1], hp, lp);
        *(uint32_t*)(Xhi + row*SA64*2 + i*4) = hp;
        *(uint32_t*)(Xlo + row*SA64*2 + i*4) = lp;
    }
}
// plain row (no LN) -> g_x + pack
__device__ __forceinline__ void row_store_pack(const float* sOut, int node, int row,
                                               char* Xhi, char* Xlo){
    float g[H];
#pragma unroll
    for (int i = 0; i < H; i++) g[i] = sOut[row*66 + i];
    float4* op = (float4*)(g_x + (size_t)node * H);
#pragma unroll
    for (int i = 0; i < 16; i++)
        op[i] = make_float4(g[4*i+0], g[4*i+1], g[4*i+2], g[4*i+3]);
#pragma unroll
    for (int i = 0; i < 32; i++){
        uint32_t hp, lp;
        pack2(g[2*i], g[2*i+1], hp, lp);
        *(uint32_t*)(Xhi + row*SA64*2 + i*4) = hp;
        *(uint32_t*)(Xlo + row*SA64*2 + i*4) = lp;
    }
}
// qkv from packed X via packed tiles t0..t0+2
__device__ __forceinline__ void qkv_from_x(char* Xhi, char* Xlo, char* Bhi, char* Blo,
                                           int t0, int node0, int wid, int lane, int tid){
    float* outs[3] = { g_q, g_k, g_v };
#pragma unroll
    for (int m = 0; m < 3; m++){
        __syncthreads();
        stage_Bimg(t0 + m, Bhi, tid);
        __syncthreads();
        float acc[8][4]; zero8(acc);
        mma_loop<4>(Xhi, Xlo, Bhi, Blo, lane, wid*16, acc);
        store_frags8(outs[m] + (size_t)node0 * H, H, wid*16, lane, acc);
    }
}

// ---------------- weight prep: pack all tiles once ----------------
__global__ void k_prep(const float* __restrict__ Win, const float* __restrict__ Wq,
                       const float* __restrict__ Wk, const float* __restrict__ Wv,
                       const float* __restrict__ Wo, const float* __restrict__ W1,
                       const float* __restrict__ W2){
    int t = blockIdx.x;
    const float* src; int ns, Ksrc;
    if (t == 0){ src = Win; ns = 64; Ksrc = FIN; }
    else {
        int l = (t-1)/8, j = (t-1)%8;
        if (j < 3){ const float* ws[3] = {Wq,Wk,Wv}; src = ws[j] + l*H*H; ns = 64; Ksrc = 64; }
        else if (j == 3){ src = Wo + l*H*H; ns = 64; Ksrc = 64; }
        else if (j < 6){ src = W1 + l*H*2*H + (j-4)*64; ns = 128; Ksrc = 64; }
        else { src = W2 + l*2*H*H + (j-6)*64*64; ns = 64; Ksrc = 64; }
    }
    char* dst = g_wimg + (size_t)t * TILE_B;
    for (int idx = threadIdx.x; idx < 64*32; idx += 256){
        int n = idx >> 5, p = idx & 31, k = 2*p;
        float v0 = (k   < Ksrc) ? __ldg(src + (size_t)k*ns + n)     : 0.f;
        float v1 = (k+1 < Ksrc) ? __ldg(src + (size_t)(k+1)*ns + n) : 0.f;
        uint32_t hp, lp;
        pack2(v0, v1, hp, lp);
        *(uint32_t*)(dst + n*SA64*2 + k*2) = hp;
        *(uint32_t*)(dst + B64_B + n*SA64*2 + k*2) = lp;
    }
}

// ---------------- CSR build (parallel scan) ----------------
__global__ void k_zero_deg(){
    int i = blockIdx.x * 256 + threadIdx.x;
    if (i < TOTN) g_deg[i] = 0;
}
__global__ void k_hist(const int* __restrict__ edst){
    int e = blockIdx.x * 256 + threadIdx.x;
    if (e < NEDGE) atomicAdd(&g_deg[edst[e]], 1);
}
// phase 1: block-local exclusive scan over 1024 elems (Hillis-Steele)
__global__ __launch_bounds__(1024) void k_scan1(){
    __shared__ int s[1024];
    int tid = threadIdx.x;
    int i = blockIdx.x * 1024 + tid;
    int d = g_deg[i];
    s[tid] = d;
    __syncthreads();
#pragma unroll
    for (int off = 1; off < 1024; off <<= 1){
        int v = (tid >= off) ? s[tid - off] : 0;
        __syncthreads();
        s[tid] += v;
        __syncthreads();
    }
    g_rowptr[i] = s[tid] - d;           // local exclusive prefix
    if (tid == 1023) g_bsum[blockIdx.x] = s[1023];
}
// phase 2: serial scan of 125 block sums (tiny)
__global__ void k_scan2(){
    if (threadIdx.x == 0){
        int run = 0;
        for (int b = 0; b < SCAN_BLKS; b++){ g_boff[b] = run; run += g_bsum[b]; }
        g_rowptr[TOTN] = run;
    }
}
// phase 3: add block offsets, init cursor
__global__ __launch_bounds__(1024) void k_scan3(){
    int i = blockIdx.x * 1024 + threadIdx.x;
    int v = g_rowptr[i] + g_boff[blockIdx.x];
    g_rowptr[i] = v;
    g_cursor[i] = v;
}
__global__ void k_scatter(const int* __restrict__ esrc, const int* __restrict__ edst){
    int e = blockIdx.x * 256 + threadIdx.x;
    if (e < NEDGE){
        int d = edst[e];
        int pos = atomicAdd(&g_cursor[d], 1);
        g_srcs[pos] = esrc[e];
    }
}

// ---------------- fused input + layer-0 qkv ----------------
__global__ __launch_bounds__(NTHR) void k_in_qkv(const float* __restrict__ nf){
    extern __shared__ __align__(16) char sm[];
    char* Xhi = sm + R_X;  char* Xlo = Xhi + A64_B;
    char* Bhi = sm + R_B;  char* Blo = Bhi + B64_B;
    char* Hhi = sm + R_H;  char* Hlo = Hhi + A64_B;
    int tid = threadIdx.x, wid = tid >> 5, lane = tid & 31;
    int node0 = blockIdx.x * BM;

    stage_A<FIN>(nf + (size_t)node0 * FIN, FIN, Hhi, Hlo, tid);
    stage_Bimg(0, Bhi, tid);
    __syncthreads();
    float acc[8][4]; zero8(acc);
    mma_loop<2>(Hhi, Hlo, Bhi, Blo, lane, wid*16, acc);
    __syncthreads();
    float* sOut = (float*)(sm + R_H);
    stage_frags8(sOut, wid*16, lane, acc);
    __syncthreads();
    if (tid < 128) row_store_pack(sOut, node0 + tid, tid, Xhi, Xlo);

    qkv_from_x(Xhi, Xlo, Bhi, Blo, 1, node0, wid, lane, tid);
}

// ---------------- fused layer: Wo+LN1+FFN1+FFN2+LN2 (+next qkv) ----------------
__global__ __launch_bounds__(NTHR) void k_layer(int l,
                                                const float* __restrict__ lg1,
                                                const float* __restrict__ lb1,
                                                const float* __restrict__ b1,
                                                const float* __restrict__ b2,
                                                const float* __restrict__ lg2,
                                                const float* __restrict__ lb2,
                                                int last){
    extern __shared__ __align__(16) char sm[];
    char* Xhi = sm + R_X;  char* Xlo = Xhi + A64_B;
    char* Bhi = sm + R_B;  char* Blo = Bhi + B64_B;
    char* Hhi = sm + R_H;  char* Hlo = Hhi + A64_B;
    int tid = threadIdx.x, wid = tid >> 5, lane = tid & 31;
    int node0 = blockIdx.x * BM;
    int tb = 1 + l*8;

    // phase 1: attn_out = agg @ Wo ; x = LN1(x + attn_out)
    stage_A<H>(g_agg + (size_t)node0 * H, H, Hhi, Hlo, tid);
    stage_Bimg(tb + 3, Bhi, tid);
    __syncthreads();
    {
        float acc[8][4]; zero8(acc);
        mma_loop<4>(Hhi, Hlo, Bhi, Blo, lane, wid*16, acc);
        __syncthreads();
        float* sOut = (float*)(sm + R_H);
        stage_frags8(sOut, wid*16, lane, acc);
        __syncthreads();
        if (tid < 128) ln_pack_row(sOut, node0 + tid, tid, nullptr, lg1, lb1, Xhi, Xlo);
        __syncthreads();
    }

    // phase 2: interleaved FFN1 halves + FFN2 K-chunks; hid stays in smem
    float acc2[8][4]; zero8(acc2);
#pragma unroll
    for (int h = 0; h < 2; h++){
        stage_Bimg(tb + 4 + h, Bhi, tid);
        __syncthreads();
        float acc1[8][4]; zero8(acc1);
        mma_loop<4>(Xhi, Xlo, Bhi, Blo, lane, wid*16, acc1);
        __syncthreads();
        frag_relu_pack(Hhi, Hlo, wid*16, lane, acc1, b1 + h*64);
        stage_Bimg(tb + 6 + h, Bhi, tid);
        __syncthreads();
        mma_loop<4>(Hhi, Hlo, Bhi, Blo, lane, wid*16, acc2);
        __syncthreads();
    }
    // phase 3: x = LN2(x + h@W2 + b2)
    {
        float* sOut = (float*)(sm + R_H);
        stage_frags8(sOut, wid*16, lane, acc2);
        __syncthreads();
        if (tid < 128) ln_pack_row(sOut, node0 + tid, tid, b2, lg2, lb2, Xhi, Xlo);
    }
    // phase 4: qkv for next layer
    if (!last)
        qkv_from_x(Xhi, Xlo, Bhi, Blo, tb + 8, node0, wid, lane, tid);
}

// ---------------- warp-per-node attention (online softmax) ----------------
__global__ __launch_bounds__(256) void k_attn(){
    int warp = (blockIdx.x * 256 + threadIdx.x) >> 5;
    int lane = threadIdx.x & 31;
    if (warp >= TOTN) return;
    int node = warp;
    float2 q = *(const float2*)(g_q + (size_t)node * H + 2*lane);
    int s0 = g_rowptr[node], s1 = g_rowptr[node + 1];
    float m = -1e30f, den = 0.f, ax = 0.f, ay = 0.f;
    for (int e = s0; e < s1; e++){
        int src = g_srcs[e];
        float2 kk = *(const float2*)(g_k + (size_t)src * H + 2*lane);
        float2 vv = *(const float2*)(g_v + (size_t)src * H + 2*lane);
        float p = q.x * kk.x + q.y * kk.y;
        p += __shfl_xor_sync(0xffffffffu, p, 1);
        p += __shfl_xor_sync(0xffffffffu, p, 2);
        p += __shfl_xor_sync(0xffffffffu, p, 4);
        float s = p * 0.25f;
        float mn = fmaxf(m, s);
        float scale = __expf(m - mn);
        float w = __expf(s - mn);
        den = den * scale + w;
        ax = ax * scale + w * vv.x;
        ay = ay * scale + w * vv.y;
        m = mn;
    }
    float inv = 1.f / (den + 1e-9f);
    *(float2*)(g_agg + (size_t)node * H + 2*lane) = make_float2(ax * inv, ay * inv);
}

// ---------------- readout + heads ----------------
__global__ void k_gat(const int* __restrict__ an, const float* __restrict__ Wr,
                      const float* __restrict__ br){
    __shared__ float sW[H*ACT];
    __shared__ float sb[ACT];
    int tid = threadIdx.x;
    for (int i = tid; i < H*ACT; i += 128) sW[i] = Wr[i];
    if (tid < ACT) sb[tid] = br[tid];
    __syncthreads();
    int b = tid;
    int node = an[b];
    float acc[ACT];
#pragma unroll
    for (int j = 0; j < ACT; j++) acc[j] = sb[j];
    for (int i = 0; i < H; i++){
        float xi = g_x[(size_t)node * H + i];
#pragma unroll
        for (int j = 0; j < ACT; j++) acc[j] += xi * sW[i*ACT + j];
    }
#pragma unroll
    for (int j = 0; j < ACT; j++) g_gat[b*ACT + j] = acc[j];
}

__global__ __launch_bounds__(512) void k_policy1(const float* __restrict__ obs,
                                                 const float* __restrict__ Wp1,
                                                 const float* __restrict__ bp1){
    __shared__ float sr[ACT + OBSD];
    int b = blockIdx.x;
    for (int i = threadIdx.x; i < ACT; i += 512) sr[i] = g_gat[b*ACT + i];
    for (int i = threadIdx.x; i < OBSD; i += 512) sr[ACT + i] = obs[(size_t)b*OBSD + i];
    __syncthreads();
    int j = threadIdx.x;
    const float* W = Wp1 + j;
    float a0 = 0, a1 = 0, a2 = 0, a3 = 0;
    int i = 0;
    const int K = ACT + OBSD;
    for (; i + 3 < K; i += 4){
        a0 += sr[i+0] * W[(size_t)(i+0)*HS];
        a1 += sr[i+1] * W[(size_t)(i+1)*HS];
        a2 += sr[i+2] * W[(size_t)(i+2)*HS];
        a3 += sr[i+3] * W[(size_t)(i+3)*HS];
    }
    for (; i < K; i++) a0 += sr[i] * W[(size_t)i*HS];
    g_feat[b*HS + j] = tanhf(a0 + a1 + a2 + a3 + bp1[j]);
}

__global__ __launch_bounds__(512) void k_policy2(const float* __restrict__ Wp2,
                                                 const float* __restrict__ bp2){
    __shared__ float sr[HS];
    int b = blockIdx.x;
    for (int i = threadIdx.x; i < HS; i += 512) sr[i] = g_feat[b*HS + i];
    __syncthreads();
    int j = threadIdx.x;
    const float* W = Wp2 + j;
    float a0 = 0, a1 = 0, a2 = 0, a3 = 0;
    for (int i = 0; i < HS; i += 4){
        a0 += sr[i+0] * W[(size_t)(i+0)*HS];
        a1 += sr[i+1] * W[(size_t)(i+1)*HS];
        a2 += sr[i+2] * W[(size_t)(i+2)*HS];
        a3 += sr[i+3] * W[(size_t)(i+3)*HS];
    }
    g_feat2[b*HS + j] = tanhf(a0 + a1 + a2 + a3 + bp2[j]);
}

__global__ void k_logits(const float* __restrict__ Wlog, const float* __restrict__ blog,
                         float* __restrict__ out){
    int b = blockIdx.x;
    int j = threadIdx.x;
    if (j >= NOUTD) return;
    float acc = blog[j];
    for (int i = 0; i < HS; i++) acc += g_feat2[b*HS + i] * Wlog[i*NOUTD + j];
    out[b*NOUTD + j] = acc;
}

__global__ __launch_bounds__(VHD) void k_value1(const float* __restrict__ obs,
                                                const float* __restrict__ Wv1,
                                                const float* __restrict__ bv1){
    __shared__ float sr[OBSD];
    int b = blockIdx.x;
    for (int i = threadIdx.x; i < OBSD; i += VHD) sr[i] = obs[(size_t)b*OBSD + i];
    __syncthreads();
    int j = threadIdx.x;
    const float* W = Wv1 + j;
    float a0 = 0, a1 = 0, a2 = 0, a3 = 0;
    for (int i = 0; i < OBSD; i += 4){
        a0 += sr[i+0] * W[(size_t)(i+0)*VHD];
        a1 += sr[i+1] * W[(size_t)(i+1)*VHD];
        a2 += sr[i+2] * W[(size_t)(i+2)*VHD];
        a3 += sr[i+3] * W[(size_t)(i+3)*VHD];
    }
    g_vh[b*VHD + j] = tanhf(a0 + a1 + a2 + a3 + bv1[j]);
}

__global__ __launch_bounds__(VHD) void k_value2(const float* __restrict__ Wv2,
                                                const float* __restrict__ bv2){
    __shared__ float sr[VHD];
    int b = blockIdx.x;
    sr[threadIdx.x] = g_vh[b*VHD + threadIdx.x];
    __syncthreads();
    int j = threadIdx.x;
    const float* W = Wv2 + j;
    float a0 = 0, a1 = 0, a2 = 0, a3 = 0;
    for (int i = 0; i < VHD; i += 4){
        a0 += sr[i+0] * W[(i+0)*VHD];
        a1 += sr[i+1] * W[(i+1)*VHD];
        a2 += sr[i+2] * W[(i+2)*VHD];
        a3 += sr[i+3] * W[(i+3)*VHD];
    }
    g_vh2[b*VHD + j] = tanhf(a0 + a1 + a2 + a3 + bv2[j]);
}

__global__ void k_valueout(const float* __restrict__ Wvo, const float* __restrict__ bvo,
                           float* __restrict__ out){
    int b = threadIdx.x;
    float acc = bvo[0];
    for (int i = 0; i < VHD; i++) acc += g_vh2[b*VHD + i] * Wvo[i];
    out[BATCH*NOUTD + b] = acc;
}

// ---------------- launch ----------------
extern "C" void kernel_launch(void* const* d_in, const int* in_sizes, int n_in,
                              void* d_out, int out_size){
    const float* node_feats = (const float*)d_in[0];
    const float* obs        = (const float*)d_in[1];
    const int*   edge_src   = (const int*)  d_in[2];
    const int*   edge_dst   = (const int*)  d_in[3];
    const int*   agent      = (const int*)  d_in[4];
    const float* W_in  = (const float*)d_in[5];
    const float* Wq    = (const float*)d_in[6];
    const float* Wk    = (const float*)d_in[7];
    const float* Wv    = (const float*)d_in[8];
    const float* Wo    = (const float*)d_in[9];
    const float* ln1g  = (const float*)d_in[10];
    const float* ln1b  = (const float*)d_in[11];
    const float* W1    = (const float*)d_in[12];
    const float* b1    = (const float*)d_in[13];
    const float* W2    = (const float*)d_in[14];
    const float* b2    = (const float*)d_in[15];
    const float* ln2g  = (const float*)d_in[16];
    const float* ln2b  = (const float*)d_in[17];
    const float* Wr    = (const float*)d_in[18];
    const float* br    = (const float*)d_in[19];
    const float* Wp1   = (const float*)d_in[20];
    const float* bp1   = (const float*)d_in[21];
    const float* Wp2   = (const float*)d_in[22];
    const float* bp2   = (const float*)d_in[23];
    const float* Wlog  = (const float*)d_in[24];
    const float* blog  = (const float*)d_in[25];
    const float* Wv1   = (const float*)d_in[26];
    const float* bv1   = (const float*)d_in[27];
    const float* Wv2   = (const float*)d_in[28];
    const float* bv2   = (const float*)d_in[29];
    const float* Wvo   = (const float*)d_in[30];
    const float* bvo   = (const float*)d_in[31];
    float* out = (float*)d_out;

    cudaFuncSetAttribute((const void*)k_in_qkv, cudaFuncAttributeMaxDynamicSharedMemorySize, SM_LAYER);
    cudaFuncSetAttribute((const void*)k_layer,  cudaFuncAttributeMaxDynamicSharedMemorySize, SM_LAYER);

    k_prep<<<NTILES, 256>>>(W_in, Wq, Wk, Wv, Wo, W1, W2);
    k_zero_deg<<<(TOTN + 255)/256, 256>>>();
    k_hist<<<(NEDGE + 255)/256, 256>>>(edge_dst);
    k_scan1<<<SCAN_BLKS, 1024>>>();
    k_scan2<<<1, 32>>>();
    k_scan3<<<SCAN_BLKS, 1024>>>();
    k_in_qkv<<<NB, NTHR, SM_LAYER>>>(node_feats);
    k_scatter<<<(NEDGE + 255)/256, 256>>>(edge_src, edge_dst);

    for (int l = 0; l < LAYERS; l++){
        k_attn<<<(TOTN*32 + 255)/256, 256>>>();
        k_layer<<<NB, NTHR, SM_LAYER>>>(l, ln1g + l*H, ln1b + l*H,
                                        b1 + l*2*H, b2 + l*H,
                                        ln2g + l*H, ln2b + l*H,
                                        (l == LAYERS-1) ? 1 : 0);
    }

    k_gat<<<1, 128>>>(agent, Wr, br);
    k_policy1<<<BATCH, 512>>>(obs, Wp1, bp1);
    k_policy2<<<BATCH, 512>>>(Wp2, bp2);
    k_logits<<<BATCH, 32>>>(Wlog, blog, out);
    k_value1<<<BATCH, VHD>>>(obs, Wv1, bv1);
    k_value2<<<BATCH, VHD>>>(Wv2, bv2);
    k_valueout<<<1, BATCH>>>(Wvo, bvo, out);
}